// round 14
// baseline (speedup 1.0000x reference)
#include <cuda_runtime.h>
#include <cuda_fp16.h>
#include <math.h>
#include <stdint.h>

// ---------------- problem constants ----------------
#define NB    8
#define NC    512
#define NHW   1024
#define NTOK  8192
#define ND    512
#define NDC   768
#define NL    77
#define NHEAD 8
#define HDIM  64
#define NFF   2048
#define EPSV  1e-5f

// ---------------- scratch ----------------
__device__ float  g_h  [(size_t)NTOK*ND];
__device__ float  g_po [(size_t)NTOK*ND];
__device__ __half g_xn [(size_t)NTOK*ND];
__device__ __half g_hn [(size_t)NTOK*ND];
__device__ __half g_h16[(size_t)NTOK*ND];
__device__ __half g_qkv[(size_t)NTOK*1536];
__device__ __half g_q  [(size_t)NTOK*ND];
__device__ __half g_kv [(size_t)640*1024];
__device__ __half g_ao [(size_t)NTOK*ND];
__device__ __half g_ff [(size_t)NTOK*NFF];
__device__ __half g_w16[4980736];
__device__ __half g_ctx16[616*768];
__device__ float  g_gmean[NB*32];
__device__ float  g_grstd[NB*32];

// w16 pool offsets (halves)
#define WT_PIN  0
#define WT_QKV  262144
#define WT_O1   1048576
#define WT_Q2   1310720
#define WT_O2   1572864
#define WT_POUT 1835008
#define WT_KV2  2097152
#define WT_FF1  2883584
#define WT_FF2  3932160

// ---------------- PTX helpers ----------------
__device__ __forceinline__ uint32_t smem_u32(const void* p) {
    uint32_t a;
    asm("{ .reg .u64 t; cvta.to.shared.u64 t, %1; cvt.u32.u64 %0, t; }" : "=r"(a) : "l"(p));
    return a;
}
__device__ __forceinline__ uint32_t h2_u32(__half2 h) {
    union { __half2 h; uint32_t u; } c;
    c.h = h;
    return c.u;
}
__device__ __forceinline__ void cp16(uint32_t dst, const void* src, bool pred) {
    int sz = pred ? 16 : 0;
    asm volatile("cp.async.cg.shared.global [%0], [%1], 16, %2;\n" :: "r"(dst), "l"(src), "r"(sz));
}
__device__ __forceinline__ void ldsm4(uint32_t& r0, uint32_t& r1, uint32_t& r2, uint32_t& r3,
                                      uint32_t a) {
    asm volatile("ldmatrix.sync.aligned.m8n8.x4.shared.b16 {%0,%1,%2,%3}, [%4];"
                 : "=r"(r0), "=r"(r1), "=r"(r2), "=r"(r3) : "r"(a));
}
__device__ __forceinline__ void ldsm4t(uint32_t& r0, uint32_t& r1, uint32_t& r2, uint32_t& r3,
                                       uint32_t a) {
    asm volatile("ldmatrix.sync.aligned.m8n8.x4.trans.shared.b16 {%0,%1,%2,%3}, [%4];"
                 : "=r"(r0), "=r"(r1), "=r"(r2), "=r"(r3) : "r"(a));
}
#define MMA_F16(acc, a0,a1,a2,a3, b0,b1) \
    asm volatile("mma.sync.aligned.m16n8k16.row.col.f32.f16.f16.f32 " \
        "{%0,%1,%2,%3}, {%4,%5,%6,%7}, {%8,%9}, {%0,%1,%2,%3};" \
        : "+f"((acc)[0]), "+f"((acc)[1]), "+f"((acc)[2]), "+f"((acc)[3]) \
        : "r"(a0), "r"(a1), "r"(a2), "r"(a3), "r"(b0), "r"(b1))

#define SAH 40                  // A smem row stride (halves)
#define SBH 136                 // B smem row stride (halves)

// ================= big fp16 GEMM: 256x128 CTA tile ========================
// C = A[M,K] @ B[K,N]. 8 warps 4(M)x2(N), warp tile 64x64. 3-stage cp.async.
#define BAH (256*SAH)           // 10240 halves
#define BBH (32*SBH)            // 4352
#define BSTH (BAH + BBH)
#define GB_SMEM (3*BSTH*2)

template<int OUTMODE>
__global__ __launch_bounds__(256, 1)
void hgemm_big_k(const __half* __restrict__ A, const __half* __restrict__ Bm,
                 float* __restrict__ C, __half* __restrict__ C16,
                 int M, int K, int lda, int ldb, int ldc,
                 const float* __restrict__ bias, const float* __restrict__ res,
                 int gelu) {
    extern __shared__ __half smh[];

    int tid = threadIdx.x;
    int warp = tid >> 5, lane = tid & 31;
    int wm = warp & 3, wn = warp >> 2;
    int lr = lane >> 2, lc = lane & 3;
    int l8 = lane & 7, grp = lane >> 3;
    int m0 = blockIdx.y * 256, n0 = blockIdx.x * 128;

    float acc[4][8][4];
    #pragma unroll
    for (int i = 0; i < 4; i++)
        #pragma unroll
        for (int j = 0; j < 8; j++)
            #pragma unroll
            for (int l = 0; l < 4; l++) acc[i][j][l] = 0.f;

    int KT = K >> 5;

    auto load_tile = [&](int st, int kt) {
        __half* As = smh + st * BSTH;
        __half* Bs = As + BAH;
        int k0 = kt << 5;
        #pragma unroll
        for (int i = 0; i < 4; i++) {      // A: 256 rows x 4 chunks
            int idx = tid + i * 256;
            int r = idx >> 2, c = idx & 3;
            int gm = m0 + r;
            int gs = gm < M ? gm : M - 1;
            cp16(smem_u32(As + r * SAH + c * 8),
                 A + (size_t)gs * lda + k0 + c * 8, gm < M);
        }
        #pragma unroll
        for (int i = 0; i < 2; i++) {      // B: 32 k-rows x 16 chunks
            int idx = tid + i * 256;
            int r = idx >> 4, c = idx & 15;
            cp16(smem_u32(Bs + r * SBH + c * 8),
                 Bm + (size_t)(k0 + r) * ldb + n0 + c * 8, true);
        }
        asm volatile("cp.async.commit_group;\n" ::: "memory");
    };

    load_tile(0, 0);
    load_tile(1, 1 < KT ? 1 : 0);

    uint32_t aoff[4], boff[4];
    #pragma unroll
    for (int mt = 0; mt < 4; mt++) {
        int arow = wm * 64 + mt * 16 + (grp & 1) * 8 + l8;
        aoff[mt] = (arow * SAH + (grp >> 1) * 8) * 2;
    }
    #pragma unroll
    for (int nf2 = 0; nf2 < 4; nf2++) {
        int brow = (grp & 1) * 8 + l8;
        int bcol = wn * 64 + nf2 * 16 + (grp >> 1) * 8;
        boff[nf2] = (BAH + brow * SBH + bcol) * 2;
    }

    for (int kt = 0; kt < KT; kt++) {
        if (kt + 1 < KT) { asm volatile("cp.async.wait_group 1;\n" ::: "memory"); }
        else             { asm volatile("cp.async.wait_group 0;\n" ::: "memory"); }
        __syncthreads();
        if (kt + 2 < KT) load_tile((kt + 2) % 3, kt + 2);

        uint32_t sbase = smem_u32(smh + (kt % 3) * BSTH);
        #pragma unroll
        for (int s16 = 0; s16 < 2; s16++) {
            uint32_t ka = sbase + s16 * 32;
            uint32_t kb = sbase + s16 * 16 * SBH * 2;
            uint32_t a[4][4];
            #pragma unroll
            for (int mt = 0; mt < 4; mt++)
                ldsm4(a[mt][0], a[mt][1], a[mt][2], a[mt][3], ka + aoff[mt]);
            uint32_t bq[8][2];
            #pragma unroll
            for (int nf2 = 0; nf2 < 4; nf2++) {
                uint32_t r0, r1, r2, r3;
                ldsm4t(r0, r1, r2, r3, kb + boff[nf2]);
                bq[nf2 * 2][0] = r0;     bq[nf2 * 2][1] = r1;
                bq[nf2 * 2 + 1][0] = r2; bq[nf2 * 2 + 1][1] = r3;
            }
            #pragma unroll
            for (int mt = 0; mt < 4; mt++)
                #pragma unroll
                for (int nt = 0; nt < 8; nt++)
                    MMA_F16(acc[mt][nt], a[mt][0], a[mt][1], a[mt][2], a[mt][3],
                            bq[nt][0], bq[nt][1]);
        }
    }

    #pragma unroll
    for (int mt = 0; mt < 4; mt++) {
        #pragma unroll
        for (int nt = 0; nt < 8; nt++) {
            int row0 = m0 + wm * 64 + mt * 16 + lr;
            int col0 = n0 + wn * 64 + nt * 8 + 2 * lc;
            #pragma unroll
            for (int hf = 0; hf < 2; hf++) {
                int gm = row0 + hf * 8;
                if (gm >= M) continue;
                float r0 = acc[mt][nt][hf * 2], r1 = acc[mt][nt][hf * 2 + 1];
                if (bias) { r0 += bias[col0]; r1 += bias[col0 + 1]; }
                if (res) {
                    r0 += res[(size_t)gm * ldc + col0];
                    r1 += res[(size_t)gm * ldc + col0 + 1];
                }
                if (gelu) {
                    r0 = 0.5f * r0 * (1.f + erff(r0 * 0.70710678118654752f));
                    r1 = 0.5f * r1 * (1.f + erff(r1 * 0.70710678118654752f));
                }
                if (OUTMODE == 0 || OUTMODE == 2) {
                    C[(size_t)gm * ldc + col0] = r0;
                    C[(size_t)gm * ldc + col0 + 1] = r1;
                }
                if (OUTMODE >= 1)
                    *(__half2*)&C16[(size_t)gm * ldc + col0] = __floats2half2_rn(r0, r1);
            }
        }
    }
}

// ================= small fp16 GEMM (128x128) — for ctx KV only ============
#define AH  (128*SAH)
#define BH  (32*SBH)
#define STH (AH + BH)
#define G_SMEM (3*STH*2)

__global__ __launch_bounds__(256, 2)
void hgemm_k(const __half* __restrict__ A, const __half* __restrict__ Bm,
             __half* __restrict__ C16,
             int M, int K, int lda, int ldb, int ldc) {
    extern __shared__ __half smh[];

    int tid = threadIdx.x;
    int warp = tid >> 5, lane = tid & 31;
    int wm = warp & 3, wn = warp >> 2;
    int lr = lane >> 2, lc = lane & 3;
    int l8 = lane & 7, grp = lane >> 3;
    int m0 = blockIdx.y * 128, n0 = blockIdx.x * 128;

    float acc[2][8][4];
    #pragma unroll
    for (int i = 0; i < 2; i++)
        #pragma unroll
        for (int j = 0; j < 8; j++)
            #pragma unroll
            for (int l = 0; l < 4; l++) acc[i][j][l] = 0.f;

    int KT = K >> 5;

    auto load_tile = [&](int st, int kt) {
        __half* As = smh + st * STH;
        __half* Bs = As + AH;
        int k0 = kt << 5;
        #pragma unroll
        for (int i = 0; i < 2; i++) {
            int idx = tid + i * 256;
            int r = idx >> 2, c = idx & 3;
            int gm = m0 + r;
            int gs = gm < M ? gm : M - 1;
            cp16(smem_u32(As + r * SAH + c * 8),
                 A + (size_t)gs * lda + k0 + c * 8, gm < M);
        }
        #pragma unroll
        for (int i = 0; i < 2; i++) {
            int idx = tid + i * 256;
            int r = idx >> 4, c = idx & 15;
            cp16(smem_u32(Bs + r * SBH + c * 8),
                 Bm + (size_t)(k0 + r) * ldb + n0 + c * 8, true);
        }
        asm volatile("cp.async.commit_group;\n" ::: "memory");
    };

    load_tile(0, 0);
    load_tile(1, 1 < KT ? 1 : 0);

    uint32_t aoff[2], boff[4];
    #pragma unroll
    for (int mt = 0; mt < 2; mt++) {
        int arow = wm * 32 + mt * 16 + (grp & 1) * 8 + l8;
        aoff[mt] = (arow * SAH + (grp >> 1) * 8) * 2;
    }
    #pragma unroll
    for (int nf2 = 0; nf2 < 4; nf2++) {
        int brow = (grp & 1) * 8 + l8;
        int bcol = wn * 64 + nf2 * 16 + (grp >> 1) * 8;
        boff[nf2] = (AH + brow * SBH + bcol) * 2;
    }

    for (int kt = 0; kt < KT; kt++) {
        if (kt + 1 < KT) { asm volatile("cp.async.wait_group 1;\n" ::: "memory"); }
        else             { asm volatile("cp.async.wait_group 0;\n" ::: "memory"); }
        __syncthreads();
        if (kt + 2 < KT) load_tile((kt + 2) % 3, kt + 2);

        uint32_t sbase = smem_u32(smh + (kt % 3) * STH);
        #pragma unroll
        for (int s16 = 0; s16 < 2; s16++) {
            uint32_t ka = sbase + s16 * 32;
            uint32_t kb = sbase + s16 * 16 * SBH * 2;
            uint32_t a[2][4];
            ldsm4(a[0][0], a[0][1], a[0][2], a[0][3], ka + aoff[0]);
            ldsm4(a[1][0], a[1][1], a[1][2], a[1][3], ka + aoff[1]);
            uint32_t bq[8][2];
            #pragma unroll
            for (int nf2 = 0; nf2 < 4; nf2++) {
                uint32_t r0, r1, r2, r3;
                ldsm4t(r0, r1, r2, r3, kb + boff[nf2]);
                bq[nf2 * 2][0] = r0;     bq[nf2 * 2][1] = r1;
                bq[nf2 * 2 + 1][0] = r2; bq[nf2 * 2 + 1][1] = r3;
            }
            #pragma unroll
            for (int mt = 0; mt < 2; mt++)
                #pragma unroll
                for (int nt = 0; nt < 8; nt++)
                    MMA_F16(acc[mt][nt], a[mt][0], a[mt][1], a[mt][2], a[mt][3],
                            bq[nt][0], bq[nt][1]);
        }
    }

    #pragma unroll
    for (int mt = 0; mt < 2; mt++) {
        #pragma unroll
        for (int nt = 0; nt < 8; nt++) {
            int row0 = m0 + wm * 32 + mt * 16 + lr;
            int col0 = n0 + wn * 64 + nt * 8 + 2 * lc;
            #pragma unroll
            for (int hf = 0; hf < 2; hf++) {
                int gm = row0 + hf * 8;
                if (gm >= M) continue;
                *(__half2*)&C16[(size_t)gm * ldc + col0] =
                    __floats2half2_rn(acc[mt][nt][hf * 2], acc[mt][nt][hf * 2 + 1]);
            }
        }
    }
}

// ================= fused flash attention (fp16) ===========================
#define FS_ST 72
#define KV_STG (64*FS_ST)
#define FA_SMEM ((2*KV_STG + 2*KV_STG + 128*FS_ST) * 2)

template<int NT, int KVLEN, int KVTOK>
__global__ __launch_bounds__(256, 2)
void flash_attn_k(const __half* __restrict__ Q, const __half* __restrict__ K,
                  const __half* __restrict__ V, __half* __restrict__ O,
                  int ldq, int ldkv) {
    constexpr bool MASK = (KVLEN & 63) != 0;
    extern __shared__ __half smh[];
    __half* Ks = smh;
    __half* Vs = smh + 2 * KV_STG;
    __half* Ps = smh + 4 * KV_STG;

    int tid = threadIdx.x, warp = tid >> 5, lane = tid & 31;
    int lr = lane >> 2, lc = lane & 3;
    int l8 = lane & 7, grp = lane >> 3;
    int bq = blockIdx.x;
    int bh = blockIdx.y;
    int b = bh >> 3, hh = bh & 7;

    const __half* Qb = Q + (size_t)(b * NHW) * ldq + hh * HDIM;
    const __half* Kb = K + (size_t)(b * KVTOK) * ldkv + hh * HDIM;
    const __half* Vb = V + (size_t)(b * KVTOK) * ldkv + hh * HDIM;
    int qrow0 = bq * 128 + warp * 16;

    uint32_t qf[4][4];
    {
        const uint32_t* q0 = (const uint32_t*)(Qb + (size_t)(qrow0 + lr    ) * ldq);
        const uint32_t* q1 = (const uint32_t*)(Qb + (size_t)(qrow0 + lr + 8) * ldq);
        #pragma unroll
        for (int kf = 0; kf < 4; kf++) {
            qf[kf][0] = q0[kf * 8 + lc];
            qf[kf][1] = q1[kf * 8 + lc];
            qf[kf][2] = q0[kf * 8 + 4 + lc];
            qf[kf][3] = q1[kf * 8 + 4 + lc];
        }
    }

    float oacc[8][4];
    #pragma unroll
    for (int i = 0; i < 8; i++)
        #pragma unroll
        for (int j = 0; j < 4; j++) oacc[i][j] = 0.f;
    float m0r = -1e30f, m1r = -1e30f, l0r = 0.f, l1r = 0.f;

    auto load_kv = [&](int st, int j) {
        int t0 = j * 64;
        #pragma unroll
        for (int i = 0; i < 2; i++) {
            int idx = tid + i * 256;
            int r = idx >> 3, c = idx & 7;
            bool ok = (t0 + r) < KVLEN;
            cp16(smem_u32(Ks + st * KV_STG + r * FS_ST + c * 8),
                 Kb + (size_t)(t0 + r) * ldkv + c * 8, ok);
        }
        #pragma unroll
        for (int i = 0; i < 2; i++) {
            int idx = tid + i * 256;
            int r = idx >> 3, c = idx & 7;
            bool ok = (t0 + r) < KVLEN;
            cp16(smem_u32(Vs + st * KV_STG + r * FS_ST + c * 8),
                 Vb + (size_t)(t0 + r) * ldkv + c * 8, ok);
        }
        asm volatile("cp.async.commit_group;\n" ::: "memory");
    };

    load_kv(0, 0);
    #pragma unroll 1
    for (int j = 0; j < NT; j++) {
        int st = j & 1;
        __syncthreads();
        if (j + 1 < NT) {
            load_kv(st ^ 1, j + 1);
            asm volatile("cp.async.wait_group 1;\n" ::: "memory");
        } else {
            asm volatile("cp.async.wait_group 0;\n" ::: "memory");
        }
        __syncthreads();
        uint32_t ktb = smem_u32(Ks + st * KV_STG);
        uint32_t vtb = smem_u32(Vs + st * KV_STG);

        float sacc[8][4];
        #pragma unroll
        for (int i = 0; i < 8; i++)
            #pragma unroll
            for (int l = 0; l < 4; l++) sacc[i][l] = 0.f;
        #pragma unroll
        for (int kf = 0; kf < 4; kf++) {
            #pragma unroll
            for (int nf2 = 0; nf2 < 4; nf2++) {
                int nrow = nf2 * 16 + (grp >> 1) * 8 + l8;
                int kcol = kf * 16 + (grp & 1) * 8;
                uint32_t r0, r1, r2, r3;
                ldsm4(r0, r1, r2, r3, ktb + (nrow * FS_ST + kcol) * 2);
                MMA_F16(sacc[nf2 * 2],     qf[kf][0], qf[kf][1], qf[kf][2], qf[kf][3], r0, r1);
                MMA_F16(sacc[nf2 * 2 + 1], qf[kf][0], qf[kf][1], qf[kf][2], qf[kf][3], r2, r3);
            }
        }

        if (MASK && j == NT - 1) {
            #pragma unroll
            for (int nt = 0; nt < 8; nt++) {
                int c0 = j * 64 + nt * 8 + 2 * lc;
                if (c0     >= KVLEN) { sacc[nt][0] = -1e30f; sacc[nt][2] = -1e30f; }
                if (c0 + 1 >= KVLEN) { sacc[nt][1] = -1e30f; sacc[nt][3] = -1e30f; }
            }
        }

        float mx0 = -1e30f, mx1 = -1e30f;
        #pragma unroll
        for (int nt = 0; nt < 8; nt++) {
            mx0 = fmaxf(mx0, fmaxf(sacc[nt][0], sacc[nt][1]));
            mx1 = fmaxf(mx1, fmaxf(sacc[nt][2], sacc[nt][3]));
        }
        mx0 = fmaxf(mx0, __shfl_xor_sync(0xffffffffu, mx0, 1));
        mx0 = fmaxf(mx0, __shfl_xor_sync(0xffffffffu, mx0, 2));
        mx1 = fmaxf(mx1, __shfl_xor_sync(0xffffffffu, mx1, 1));
        mx1 = fmaxf(mx1, __shfl_xor_sync(0xffffffffu, mx1, 2));
        float mn0 = fmaxf(m0r, mx0), mn1 = fmaxf(m1r, mx1);
        float f0 = __expf(m0r - mn0), f1 = __expf(m1r - mn1);
        float s0 = 0.f, s1 = 0.f;
        int prow = warp * 16 + lr;
        uint32_t* Ps32 = (uint32_t*)Ps;
        #pragma unroll
        for (int nt = 0; nt < 8; nt++) {
            float p00 = __expf(sacc[nt][0] - mn0);
            float p01 = __expf(sacc[nt][1] - mn0);
            float p10 = __expf(sacc[nt][2] - mn1);
            float p11 = __expf(sacc[nt][3] - mn1);
            s0 += p00 + p01; s1 += p10 + p11;
            Ps32[(prow    ) * (FS_ST / 2) + nt * 4 + lc] = h2_u32(__floats2half2_rn(p00, p01));
            Ps32[(prow + 8) * (FS_ST / 2) + nt * 4 + lc] = h2_u32(__floats2half2_rn(p10, p11));
            oacc[nt][0] *= f0; oacc[nt][1] *= f0;
            oacc[nt][2] *= f1; oacc[nt][3] *= f1;
        }
        s0 += __shfl_xor_sync(0xffffffffu, s0, 1);
        s0 += __shfl_xor_sync(0xffffffffu, s0, 2);
        s1 += __shfl_xor_sync(0xffffffffu, s1, 1);
        s1 += __shfl_xor_sync(0xffffffffu, s1, 2);
        l0r = l0r * f0 + s0; l1r = l1r * f1 + s1;
        m0r = mn0; m1r = mn1;

        uint32_t psb = smem_u32(Ps);
        #pragma unroll
        for (int kf = 0; kf < 4; kf++) {
            uint32_t pa[4];
            {
                int arow = warp * 16 + (grp & 1) * 8 + l8;
                int acol = kf * 16 + (grp >> 1) * 8;
                ldsm4(pa[0], pa[1], pa[2], pa[3], psb + (arow * FS_ST + acol) * 2);
            }
            #pragma unroll
            for (int nf2 = 0; nf2 < 4; nf2++) {
                int krow = kf * 16 + (grp & 1) * 8 + l8;
                int ncol = nf2 * 16 + (grp >> 1) * 8;
                uint32_t r0, r1, r2, r3;
                ldsm4t(r0, r1, r2, r3, vtb + (krow * FS_ST + ncol) * 2);
                MMA_F16(oacc[nf2 * 2],     pa[0], pa[1], pa[2], pa[3], r0, r1);
                MMA_F16(oacc[nf2 * 2 + 1], pa[0], pa[1], pa[2], pa[3], r2, r3);
            }
        }
    }

    float inv0 = 1.f / l0r, inv1 = 1.f / l1r;
    __half* Ob = O + (size_t)(b * NHW) * ND + hh * HDIM;
    #pragma unroll
    for (int nt = 0; nt < 8; nt++) {
        int col = nt * 8 + 2 * lc;
        *(__half2*)&Ob[(size_t)(qrow0 + lr    ) * ND + col] =
            __floats2half2_rn(oacc[nt][0] * inv0, oacc[nt][1] * inv0);
        *(__half2*)&Ob[(size_t)(qrow0 + lr + 8) * ND + col] =
            __floats2half2_rn(oacc[nt][2] * inv1, oacc[nt][3] * inv1);
    }
}

// ================= small kernels =================
__device__ __forceinline__ float2 blk_reduce2(float a, float b) {
    __shared__ float sha[9], shb[9];
    int lane = threadIdx.x & 31, w = threadIdx.x >> 5;
    #pragma unroll
    for (int o = 16; o; o >>= 1) {
        a += __shfl_down_sync(0xffffffffu, a, o);
        b += __shfl_down_sync(0xffffffffu, b, o);
    }
    if (!lane) { sha[w] = a; shb[w] = b; }
    __syncthreads();
    if (threadIdx.x == 0) {
        int nw = blockDim.x >> 5;
        float ta = 0.f, tb = 0.f;
        for (int i = 0; i < nw; i++) { ta += sha[i]; tb += shb[i]; }
        sha[8] = ta; shb[8] = tb;
    }
    __syncthreads();
    float2 r = make_float2(sha[8], shb[8]);
    __syncthreads();
    return r;
}

struct CvtSegs {
    const float* src[13];
    __half* dst[13];
    int n[13];
    int cols[13];
    int dstld[13];
    float scale[13];
};
__global__ void cvt_k(CvtSegs cs) {
    int seg = blockIdx.y;
    int n = cs.n[seg];
    int cols = cs.cols[seg], dstld = cs.dstld[seg];
    float sc = cs.scale[seg];
    const float* s = cs.src[seg];
    __half* d = cs.dst[seg];
    for (int i = blockIdx.x * blockDim.x + threadIdx.x; i < n; i += gridDim.x * blockDim.x) {
        int r = i / cols, c = i - r * cols;
        d[(size_t)r * dstld + c] = __float2half(s[i] * sc);
    }
}

__global__ void gn_stats_k(const float* __restrict__ x, float* __restrict__ mean,
                           float* __restrict__ rstd) {
    int bg = blockIdx.x;
    const float* p = x + (size_t)bg * 16384;
    float s = 0.f, s2 = 0.f;
    for (int i = threadIdx.x; i < 16384; i += 256) {
        float v = p[i];
        s += v; s2 += v * v;
    }
    float2 r = blk_reduce2(s, s2);
    if (threadIdx.x == 0) {
        float mu  = r.x * (1.f / 16384.f);
        float var = r.y * (1.f / 16384.f) - mu * mu;
        mean[bg] = mu;
        rstd[bg] = rsqrtf(var + EPSV);
    }
}

__global__ void gn_apply_k(const float* __restrict__ x, const float* __restrict__ gamma,
                           const float* __restrict__ beta, const float* __restrict__ mean,
                           const float* __restrict__ rstd, __half* __restrict__ xn) {
    __shared__ float tile[32][33];
    int b = blockIdx.z;
    int c0 = blockIdx.y * 32, hw0 = blockIdx.x * 32;
    int c = c0 + threadIdx.y, hw = hw0 + threadIdx.x;
    float v = x[((size_t)b * NC + c) * NHW + hw];
    int grp = c >> 4;
    float mu = mean[b * 32 + grp], rs = rstd[b * 32 + grp];
    tile[threadIdx.y][threadIdx.x] = (v - mu) * rs * gamma[c] + beta[c];
    __syncthreads();
    xn[((size_t)b * NHW + hw0 + threadIdx.y) * ND + c0 + threadIdx.x] =
        __float2half(tile[threadIdx.x][threadIdx.y]);
}

__global__ void ln_k(const float* __restrict__ x, const float* __restrict__ g,
                     const float* __restrict__ b, __half* __restrict__ y) {
    size_t row = blockIdx.x;
    const float2* xr = (const float2*)(x + row * ND);
    int t = threadIdx.x;
    float2 v = xr[t];
    float2 r = blk_reduce2(v.x + v.y, v.x * v.x + v.y * v.y);
    float mu = r.x * (1.f / ND);
    float rs = rsqrtf(r.y * (1.f / ND) - mu * mu + EPSV);
    float n0 = (v.x - mu) * rs * g[2 * t]     + b[2 * t];
    float n1 = (v.y - mu) * rs * g[2 * t + 1] + b[2 * t + 1];
    ((__half2*)(y + row * ND))[t] = __floats2half2_rn(n0, n1);
}

__global__ void out_add_k(const float* __restrict__ t, const float* __restrict__ x_in,
                          float* __restrict__ out) {
    __shared__ float tile[32][33];
    int b = blockIdx.z;
    int c0 = blockIdx.x * 32, hw0 = blockIdx.y * 32;
    tile[threadIdx.y][threadIdx.x] =
        t[((size_t)b * NHW + hw0 + threadIdx.y) * ND + c0 + threadIdx.x];
    __syncthreads();
    size_t o = ((size_t)b * NC + c0 + threadIdx.y) * NHW + hw0 + threadIdx.x;
    out[o] = tile[threadIdx.x][threadIdx.y] + x_in[o];
}

// ================= host =================
template<int OUTMODE>
static void hgB(const __half* A, const __half* B, float* C, __half* C16,
                int M, int N, int K, int lda, int ldb, int ldc,
                const float* bias, const float* res, int gelu) {
    static bool attr_set = false;
    if (!attr_set) {
        cudaFuncSetAttribute(hgemm_big_k<OUTMODE>,
                             cudaFuncAttributeMaxDynamicSharedMemorySize, GB_SMEM);
        attr_set = true;
    }
    dim3 grid(N / 128, (M + 255) / 256);
    hgemm_big_k<OUTMODE><<<grid, 256, GB_SMEM>>>(A, B, C, C16, M, K, lda, ldb, ldc,
                                                 bias, res, gelu);
}

extern "C" void kernel_launch(void* const* d_in, const int* in_sizes, int n_in,
                              void* d_out, int out_size) {
    const float* x      = (const float*)d_in[0];
    const float* ctx    = (const float*)d_in[1];
    const float* gn_g   = (const float*)d_in[2];
    const float* gn_b   = (const float*)d_in[3];
    const float* pin_w  = (const float*)d_in[4];
    const float* pin_b  = (const float*)d_in[5];
    const float* ln1_g  = (const float*)d_in[6];
    const float* ln1_b  = (const float*)d_in[7];
    const float* q1_w   = (const float*)d_in[8];
    const float* k1_w   = (const float*)d_in[9];
    const float* v1_w   = (const float*)d_in[10];
    const float* o1_w   = (const float*)d_in[11];
    const float* o1_b   = (const float*)d_in[12];
    const float* ln2_g  = (const float*)d_in[13];
    const float* ln2_b  = (const float*)d_in[14];
    const float* q2_w   = (const float*)d_in[15];
    const float* k2_w   = (const float*)d_in[16];
    const float* v2_w   = (const float*)d_in[17];
    const float* o2_w   = (const float*)d_in[18];
    const float* o2_b   = (const float*)d_in[19];
    const float* ln3_g  = (const float*)d_in[20];
    const float* ln3_b  = (const float*)d_in[21];
    const float* ff1_w  = (const float*)d_in[22];
    const float* ff1_b  = (const float*)d_in[23];
    const float* ff2_w  = (const float*)d_in[24];
    const float* ff2_b  = (const float*)d_in[25];
    const float* pout_w = (const float*)d_in[26];
    const float* pout_b = (const float*)d_in[27];
    float* out = (float*)d_out;

    float *h, *po, *gmean, *grstd;
    __half *xn, *hn, *h16, *qkv, *q, *kv, *ao, *ff, *w16, *ctx16;
    cudaGetSymbolAddress((void**)&h,     g_h);
    cudaGetSymbolAddress((void**)&po,    g_po);
    cudaGetSymbolAddress((void**)&xn,    g_xn);
    cudaGetSymbolAddress((void**)&hn,    g_hn);
    cudaGetSymbolAddress((void**)&h16,   g_h16);
    cudaGetSymbolAddress((void**)&qkv,   g_qkv);
    cudaGetSymbolAddress((void**)&q,     g_q);
    cudaGetSymbolAddress((void**)&kv,    g_kv);
    cudaGetSymbolAddress((void**)&ao,    g_ao);
    cudaGetSymbolAddress((void**)&ff,    g_ff);
    cudaGetSymbolAddress((void**)&w16,   g_w16);
    cudaGetSymbolAddress((void**)&ctx16, g_ctx16);
    cudaGetSymbolAddress((void**)&gmean, g_gmean);
    cudaGetSymbolAddress((void**)&grstd, g_grstd);

    dim3 t32(32, 32);

    static bool attr = false;
    if (!attr) {
        cudaFuncSetAttribute(flash_attn_k<16, 1024, 1024>,
                             cudaFuncAttributeMaxDynamicSharedMemorySize, FA_SMEM);
        cudaFuncSetAttribute(flash_attn_k<2, 77, 77>,
                             cudaFuncAttributeMaxDynamicSharedMemorySize, FA_SMEM);
        cudaFuncSetAttribute(hgemm_k,
                             cudaFuncAttributeMaxDynamicSharedMemorySize, G_SMEM);
        attr = true;
    }

    // 0) fp16 conversions: weights (packed/fused, attn scale folded) + ctx
    {
        CvtSegs cs;
        const float* srcs[13] = {pin_w, q1_w, k1_w, v1_w, o1_w, q2_w, o2_w, pout_w,
                                 k2_w, v2_w, ff1_w, ff2_w, ctx};
        __half* dsts[13] = {w16 + WT_PIN, w16 + WT_QKV, w16 + WT_QKV + 512,
                            w16 + WT_QKV + 1024, w16 + WT_O1, w16 + WT_Q2,
                            w16 + WT_O2, w16 + WT_POUT,
                            w16 + WT_KV2, w16 + WT_KV2 + 512,
                            w16 + WT_FF1, w16 + WT_FF2, ctx16};
        int ns[13]   = {262144, 262144, 262144, 262144, 262144, 262144, 262144, 262144,
                        393216, 393216, 1048576, 1048576, 473088};
        int cols[13] = {512, 512, 512, 512, 512, 512, 512, 512,
                        512, 512, 2048, 512, 768};
        int lds[13]  = {512, 1536, 1536, 1536, 512, 512, 512, 512,
                        1024, 1024, 2048, 512, 768};
        float scs[13] = {1.f, 0.125f, 1.f, 1.f, 1.f, 0.125f, 1.f, 1.f,
                         1.f, 1.f, 1.f, 1.f, 1.f};
        for (int i = 0; i < 13; i++) {
            cs.src[i] = srcs[i]; cs.dst[i] = dsts[i]; cs.n[i] = ns[i];
            cs.cols[i] = cols[i]; cs.dstld[i] = lds[i]; cs.scale[i] = scs[i];
        }
        cvt_k<<<dim3(256, 13), 256>>>(cs);
    }

    // 1) GroupNorm + transpose to token-major (fp16 out)
    gn_stats_k<<<NB * 32, 256>>>(x, gmean, grstd);
    gn_apply_k<<<dim3(NHW / 32, NC / 32, NB), t32>>>(x, gn_g, gn_b, gmean, grstd, xn);

    // 2) proj_in
    hgB<0>(xn, w16 + WT_PIN, h, nullptr, NTOK, ND, ND, ND, ND, ND, pin_b, nullptr, 0);

    // 3) self-attention: fused QKV (q pre-scaled), flash, out-proj
    ln_k<<<NTOK, 256>>>(h, ln1_g, ln1_b, hn);
    hgB<1>(hn, w16 + WT_QKV, nullptr, qkv, NTOK, 1536, ND, ND, 1536, 1536,
           nullptr, nullptr, 0);
    flash_attn_k<16, 1024, 1024><<<dim3(8, 64), 256, FA_SMEM>>>(
        qkv, qkv + 512, qkv + 1024, ao, 1536, 1536);
    hgB<0>(ao, w16 + WT_O1, h, nullptr, NTOK, ND, ND, ND, ND, ND, o1_b, h, 0);

    // 4) cross-attention: q proj + fused ctx KV + flash + out-proj
    ln_k<<<NTOK, 256>>>(h, ln2_g, ln2_b, hn);
    hgB<1>(hn, w16 + WT_Q2, nullptr, q, NTOK, ND, ND, ND, ND, ND, nullptr, nullptr, 0);
    hgemm_k<<<dim3(8, 5), 256, G_SMEM>>>(ctx16, w16 + WT_KV2, kv,
                                         NB * NL, NDC, NDC, 1024, 1024);
    flash_attn_k<2, 77, 77><<<dim3(8, 64), 256, FA_SMEM>>>(
        q, kv, kv + 512, ao, 512, 1024);
    hgB<0>(ao, w16 + WT_O2, h, nullptr, NTOK, ND, ND, ND, ND, ND, o2_b, h, 0);

    // 5) feed-forward
    ln_k<<<NTOK, 256>>>(h, ln3_g, ln3_b, hn);
    hgB<1>(hn, w16 + WT_FF1, nullptr, ff, NTOK, NFF, ND, ND, NFF, NFF, ff1_b, nullptr, 1);
    hgB<2>(ff, w16 + WT_FF2, h, h16, NTOK, ND, NFF, NFF, ND, ND, ff2_b, h, 0);

    // 6) proj_out + input residual
    hgB<0>(h16, w16 + WT_POUT, po, nullptr, NTOK, NC, ND, ND, NC, NC, pout_b, nullptr, 0);
    out_add_k<<<dim3(NC / 32, NHW / 32, NB), t32>>>(po, x, out);
}

// round 16
// speedup vs baseline: 1.7313x; 1.7313x over previous
#include <cuda_runtime.h>
#include <cuda_fp16.h>
#include <math.h>
#include <stdint.h>

// ---------------- problem constants ----------------
#define NB    8
#define NC    512
#define NHW   1024
#define NTOK  8192
#define ND    512
#define NDC   768
#define NL    77
#define NHEAD 8
#define HDIM  64
#define NFF   2048
#define EPSV  1e-5f

// ---------------- scratch ----------------
__device__ float  g_h  [(size_t)NTOK*ND];
__device__ float  g_po [(size_t)NTOK*ND];
__device__ __half g_xn [(size_t)NTOK*ND];
__device__ __half g_hn [(size_t)NTOK*ND];
__device__ __half g_h16[(size_t)NTOK*ND];
__device__ __half g_qkv[(size_t)NTOK*1536];
__device__ __half g_q  [(size_t)NTOK*ND];
__device__ __half g_kv [(size_t)640*1024];
__device__ __half g_ao [(size_t)NTOK*ND];
__device__ __half g_ff [(size_t)NTOK*NFF];
__device__ __half g_w16[4980736];
__device__ __half g_ctx16[616*768];
__device__ float  g_gmean[NB*32];
__device__ float  g_grstd[NB*32];

// w16 pool offsets (halves)
#define WT_PIN  0
#define WT_QKV  262144
#define WT_O1   1048576
#define WT_Q2   1310720
#define WT_O2   1572864
#define WT_POUT 1835008
#define WT_KV2  2097152
#define WT_FF1  2883584
#define WT_FF2  3932160

// ---------------- PTX helpers ----------------
__device__ __forceinline__ uint32_t smem_u32(const void* p) {
    uint32_t a;
    asm("{ .reg .u64 t; cvta.to.shared.u64 t, %1; cvt.u32.u64 %0, t; }" : "=r"(a) : "l"(p));
    return a;
}
__device__ __forceinline__ uint32_t h2_u32(__half2 h) {
    union { __half2 h; uint32_t u; } c;
    c.h = h;
    return c.u;
}
__device__ __forceinline__ void cp16(uint32_t dst, const void* src, bool pred) {
    int sz = pred ? 16 : 0;
    asm volatile("cp.async.cg.shared.global [%0], [%1], 16, %2;\n" :: "r"(dst), "l"(src), "r"(sz));
}
__device__ __forceinline__ void ldsm4(uint32_t& r0, uint32_t& r1, uint32_t& r2, uint32_t& r3,
                                      uint32_t a) {
    asm volatile("ldmatrix.sync.aligned.m8n8.x4.shared.b16 {%0,%1,%2,%3}, [%4];"
                 : "=r"(r0), "=r"(r1), "=r"(r2), "=r"(r3) : "r"(a));
}
__device__ __forceinline__ void ldsm4t(uint32_t& r0, uint32_t& r1, uint32_t& r2, uint32_t& r3,
                                       uint32_t a) {
    asm volatile("ldmatrix.sync.aligned.m8n8.x4.trans.shared.b16 {%0,%1,%2,%3}, [%4];"
                 : "=r"(r0), "=r"(r1), "=r"(r2), "=r"(r3) : "r"(a));
}
#define MMA_F16(acc, a0,a1,a2,a3, b0,b1) \
    asm volatile("mma.sync.aligned.m16n8k16.row.col.f32.f16.f16.f32 " \
        "{%0,%1,%2,%3}, {%4,%5,%6,%7}, {%8,%9}, {%0,%1,%2,%3};" \
        : "+f"((acc)[0]), "+f"((acc)[1]), "+f"((acc)[2]), "+f"((acc)[3]) \
        : "r"(a0), "r"(a1), "r"(a2), "r"(a3), "r"(b0), "r"(b1))

// ================= fp16 warp-MMA GEMM (128x128, 2 CTAs/SM) ================
// C = A[M,K] @ B[K,N] (+bias, +res, gelu). fp16 in, fp32 accumulate.
// OUTMODE: 0=f32 C, 1=f16 C16, 2=both.
#define SAH 40                  // A smem row stride (halves)
#define SBH 136                 // B smem row stride (halves)
#define AH  (128*SAH)
#define BH  (32*SBH)
#define STH (AH + BH)
#define G_SMEM (3*STH*2)

template<int OUTMODE>
__global__ __launch_bounds__(256, 2)
void hgemm_k(const __half* __restrict__ A, const __half* __restrict__ Bm,
             float* __restrict__ C, __half* __restrict__ C16,
             int M, int K, int lda, int ldb, int ldc,
             const float* __restrict__ bias, const float* __restrict__ res,
             int gelu) {
    extern __shared__ __half smh[];

    int tid = threadIdx.x;
    int warp = tid >> 5, lane = tid & 31;
    int wm = warp & 3, wn = warp >> 2;
    int lr = lane >> 2, lc = lane & 3;
    int l8 = lane & 7, grp = lane >> 3;
    int m0 = blockIdx.y * 128, n0 = blockIdx.x * 128;

    float acc[2][8][4];
    #pragma unroll
    for (int i = 0; i < 2; i++)
        #pragma unroll
        for (int j = 0; j < 8; j++)
            #pragma unroll
            for (int l = 0; l < 4; l++) acc[i][j][l] = 0.f;

    int KT = K >> 5;

    auto load_tile = [&](int st, int kt) {
        __half* As = smh + st * STH;
        __half* Bs = As + AH;
        int k0 = kt << 5;
        #pragma unroll
        for (int i = 0; i < 2; i++) {      // A: 128 rows x 4 chunks (8 halves)
            int idx = tid + i * 256;
            int r = idx >> 2, c = idx & 3;
            int gm = m0 + r;
            int gs = gm < M ? gm : M - 1;
            cp16(smem_u32(As + r * SAH + c * 8),
                 A + (size_t)gs * lda + k0 + c * 8, gm < M);
        }
        #pragma unroll
        for (int i = 0; i < 2; i++) {      // B: 32 k-rows x 16 chunks
            int idx = tid + i * 256;
            int r = idx >> 4, c = idx & 15;
            cp16(smem_u32(Bs + r * SBH + c * 8),
                 Bm + (size_t)(k0 + r) * ldb + n0 + c * 8, true);
        }
        asm volatile("cp.async.commit_group;\n" ::: "memory");
    };

    load_tile(0, 0);
    load_tile(1, 1 < KT ? 1 : 0);

    uint32_t aoff[2], boff[4];
    #pragma unroll
    for (int mt = 0; mt < 2; mt++) {
        int arow = wm * 32 + mt * 16 + (grp & 1) * 8 + l8;
        aoff[mt] = (arow * SAH + (grp >> 1) * 8) * 2;
    }
    #pragma unroll
    for (int nf2 = 0; nf2 < 4; nf2++) {
        int brow = (grp & 1) * 8 + l8;
        int bcol = wn * 64 + nf2 * 16 + (grp >> 1) * 8;
        boff[nf2] = (AH + brow * SBH + bcol) * 2;
    }

    for (int kt = 0; kt < KT; kt++) {
        if (kt + 1 < KT) { asm volatile("cp.async.wait_group 1;\n" ::: "memory"); }
        else             { asm volatile("cp.async.wait_group 0;\n" ::: "memory"); }
        __syncthreads();
        if (kt + 2 < KT) load_tile((kt + 2) % 3, kt + 2);

        uint32_t sbase = smem_u32(smh + (kt % 3) * STH);
        #pragma unroll
        for (int s16 = 0; s16 < 2; s16++) {
            uint32_t ka = sbase + s16 * 32;
            uint32_t kb = sbase + s16 * 16 * SBH * 2;
            uint32_t a[2][4];
            ldsm4(a[0][0], a[0][1], a[0][2], a[0][3], ka + aoff[0]);
            ldsm4(a[1][0], a[1][1], a[1][2], a[1][3], ka + aoff[1]);
            uint32_t bq[8][2];
            #pragma unroll
            for (int nf2 = 0; nf2 < 4; nf2++) {
                uint32_t r0, r1, r2, r3;
                ldsm4t(r0, r1, r2, r3, kb + boff[nf2]);
                bq[nf2 * 2][0] = r0;     bq[nf2 * 2][1] = r1;
                bq[nf2 * 2 + 1][0] = r2; bq[nf2 * 2 + 1][1] = r3;
            }
            #pragma unroll
            for (int mt = 0; mt < 2; mt++)
                #pragma unroll
                for (int nt = 0; nt < 8; nt++)
                    MMA_F16(acc[mt][nt], a[mt][0], a[mt][1], a[mt][2], a[mt][3],
                            bq[nt][0], bq[nt][1]);
        }
    }

    // epilogue
    #pragma unroll
    for (int mt = 0; mt < 2; mt++) {
        #pragma unroll
        for (int nt = 0; nt < 8; nt++) {
            int row0 = m0 + wm * 32 + mt * 16 + lr;
            int col0 = n0 + wn * 64 + nt * 8 + 2 * lc;
            #pragma unroll
            for (int hf = 0; hf < 2; hf++) {
                int gm = row0 + hf * 8;
                if (gm >= M) continue;
                float r0 = acc[mt][nt][hf * 2], r1 = acc[mt][nt][hf * 2 + 1];
                if (bias) { r0 += bias[col0]; r1 += bias[col0 + 1]; }
                if (res) {
                    r0 += res[(size_t)gm * ldc + col0];
                    r1 += res[(size_t)gm * ldc + col0 + 1];
                }
                if (gelu) {
                    r0 = 0.5f * r0 * (1.f + erff(r0 * 0.70710678118654752f));
                    r1 = 0.5f * r1 * (1.f + erff(r1 * 0.70710678118654752f));
                }
                if (OUTMODE == 0 || OUTMODE == 2) {
                    C[(size_t)gm * ldc + col0] = r0;
                    C[(size_t)gm * ldc + col0 + 1] = r1;
                }
                if (OUTMODE >= 1)
                    *(__half2*)&C16[(size_t)gm * ldc + col0] = __floats2half2_rn(r0, r1);
            }
        }
    }
}

// ================= fused flash attention (fp16) ===========================
#define FS_ST 72
#define KV_STG (64*FS_ST)
#define FA_SMEM ((2*KV_STG + 2*KV_STG + 128*FS_ST) * 2)

template<int NT, int KVLEN, int KVTOK>
__global__ __launch_bounds__(256, 2)
void flash_attn_k(const __half* __restrict__ Q, const __half* __restrict__ K,
                  const __half* __restrict__ V, __half* __restrict__ O,
                  int ldq, int ldkv) {
    constexpr bool MASK = (KVLEN & 63) != 0;
    extern __shared__ __half smh[];
    __half* Ks = smh;
    __half* Vs = smh + 2 * KV_STG;
    __half* Ps = smh + 4 * KV_STG;

    int tid = threadIdx.x, warp = tid >> 5, lane = tid & 31;
    int lr = lane >> 2, lc = lane & 3;
    int l8 = lane & 7, grp = lane >> 3;
    int bq = blockIdx.x;
    int bh = blockIdx.y;
    int b = bh >> 3, hh = bh & 7;

    const __half* Qb = Q + (size_t)(b * NHW) * ldq + hh * HDIM;
    const __half* Kb = K + (size_t)(b * KVTOK) * ldkv + hh * HDIM;
    const __half* Vb = V + (size_t)(b * KVTOK) * ldkv + hh * HDIM;
    int qrow0 = bq * 128 + warp * 16;

    uint32_t qf[4][4];
    {
        const uint32_t* q0 = (const uint32_t*)(Qb + (size_t)(qrow0 + lr    ) * ldq);
        const uint32_t* q1 = (const uint32_t*)(Qb + (size_t)(qrow0 + lr + 8) * ldq);
        #pragma unroll
        for (int kf = 0; kf < 4; kf++) {
            qf[kf][0] = q0[kf * 8 + lc];
            qf[kf][1] = q1[kf * 8 + lc];
            qf[kf][2] = q0[kf * 8 + 4 + lc];
            qf[kf][3] = q1[kf * 8 + 4 + lc];
        }
    }

    float oacc[8][4];
    #pragma unroll
    for (int i = 0; i < 8; i++)
        #pragma unroll
        for (int j = 0; j < 4; j++) oacc[i][j] = 0.f;
    float m0r = -1e30f, m1r = -1e30f, l0r = 0.f, l1r = 0.f;

    auto load_kv = [&](int st, int j) {
        int t0 = j * 64;
        #pragma unroll
        for (int i = 0; i < 2; i++) {
            int idx = tid + i * 256;
            int r = idx >> 3, c = idx & 7;
            bool ok = (t0 + r) < KVLEN;
            cp16(smem_u32(Ks + st * KV_STG + r * FS_ST + c * 8),
                 Kb + (size_t)(t0 + r) * ldkv + c * 8, ok);
        }
        #pragma unroll
        for (int i = 0; i < 2; i++) {
            int idx = tid + i * 256;
            int r = idx >> 3, c = idx & 7;
            bool ok = (t0 + r) < KVLEN;
            cp16(smem_u32(Vs + st * KV_STG + r * FS_ST + c * 8),
                 Vb + (size_t)(t0 + r) * ldkv + c * 8, ok);
        }
        asm volatile("cp.async.commit_group;\n" ::: "memory");
    };

    load_kv(0, 0);
    #pragma unroll 1
    for (int j = 0; j < NT; j++) {
        int st = j & 1;
        __syncthreads();
        if (j + 1 < NT) {
            load_kv(st ^ 1, j + 1);
            asm volatile("cp.async.wait_group 1;\n" ::: "memory");
        } else {
            asm volatile("cp.async.wait_group 0;\n" ::: "memory");
        }
        __syncthreads();
        uint32_t ktb = smem_u32(Ks + st * KV_STG);
        uint32_t vtb = smem_u32(Vs + st * KV_STG);

        float sacc[8][4];
        #pragma unroll
        for (int i = 0; i < 8; i++)
            #pragma unroll
            for (int l = 0; l < 4; l++) sacc[i][l] = 0.f;
        #pragma unroll
        for (int kf = 0; kf < 4; kf++) {
            #pragma unroll
            for (int nf2 = 0; nf2 < 4; nf2++) {
                int nrow = nf2 * 16 + (grp >> 1) * 8 + l8;
                int kcol = kf * 16 + (grp & 1) * 8;
                uint32_t r0, r1, r2, r3;
                ldsm4(r0, r1, r2, r3, ktb + (nrow * FS_ST + kcol) * 2);
                MMA_F16(sacc[nf2 * 2],     qf[kf][0], qf[kf][1], qf[kf][2], qf[kf][3], r0, r1);
                MMA_F16(sacc[nf2 * 2 + 1], qf[kf][0], qf[kf][1], qf[kf][2], qf[kf][3], r2, r3);
            }
        }

        if (MASK && j == NT - 1) {
            #pragma unroll
            for (int nt = 0; nt < 8; nt++) {
                int c0 = j * 64 + nt * 8 + 2 * lc;
                if (c0     >= KVLEN) { sacc[nt][0] = -1e30f; sacc[nt][2] = -1e30f; }
                if (c0 + 1 >= KVLEN) { sacc[nt][1] = -1e30f; sacc[nt][3] = -1e30f; }
            }
        }

        float mx0 = -1e30f, mx1 = -1e30f;
        #pragma unroll
        for (int nt = 0; nt < 8; nt++) {
            mx0 = fmaxf(mx0, fmaxf(sacc[nt][0], sacc[nt][1]));
            mx1 = fmaxf(mx1, fmaxf(sacc[nt][2], sacc[nt][3]));
        }
        mx0 = fmaxf(mx0, __shfl_xor_sync(0xffffffffu, mx0, 1));
        mx0 = fmaxf(mx0, __shfl_xor_sync(0xffffffffu, mx0, 2));
        mx1 = fmaxf(mx1, __shfl_xor_sync(0xffffffffu, mx1, 1));
        mx1 = fmaxf(mx1, __shfl_xor_sync(0xffffffffu, mx1, 2));
        float mn0 = fmaxf(m0r, mx0), mn1 = fmaxf(m1r, mx1);
        float f0 = __expf(m0r - mn0), f1 = __expf(m1r - mn1);
        float s0 = 0.f, s1 = 0.f;
        int prow = warp * 16 + lr;
        uint32_t* Ps32 = (uint32_t*)Ps;
        #pragma unroll
        for (int nt = 0; nt < 8; nt++) {
            float p00 = __expf(sacc[nt][0] - mn0);
            float p01 = __expf(sacc[nt][1] - mn0);
            float p10 = __expf(sacc[nt][2] - mn1);
            float p11 = __expf(sacc[nt][3] - mn1);
            s0 += p00 + p01; s1 += p10 + p11;
            Ps32[(prow    ) * (FS_ST / 2) + nt * 4 + lc] = h2_u32(__floats2half2_rn(p00, p01));
            Ps32[(prow + 8) * (FS_ST / 2) + nt * 4 + lc] = h2_u32(__floats2half2_rn(p10, p11));
            oacc[nt][0] *= f0; oacc[nt][1] *= f0;
            oacc[nt][2] *= f1; oacc[nt][3] *= f1;
        }
        s0 += __shfl_xor_sync(0xffffffffu, s0, 1);
        s0 += __shfl_xor_sync(0xffffffffu, s0, 2);
        s1 += __shfl_xor_sync(0xffffffffu, s1, 1);
        s1 += __shfl_xor_sync(0xffffffffu, s1, 2);
        l0r = l0r * f0 + s0; l1r = l1r * f1 + s1;
        m0r = mn0; m1r = mn1;

        uint32_t psb = smem_u32(Ps);
        #pragma unroll
        for (int kf = 0; kf < 4; kf++) {
            uint32_t pa[4];
            {
                int arow = warp * 16 + (grp & 1) * 8 + l8;
                int acol = kf * 16 + (grp >> 1) * 8;
                ldsm4(pa[0], pa[1], pa[2], pa[3], psb + (arow * FS_ST + acol) * 2);
            }
            #pragma unroll
            for (int nf2 = 0; nf2 < 4; nf2++) {
                int krow = kf * 16 + (grp & 1) * 8 + l8;
                int ncol = nf2 * 16 + (grp >> 1) * 8;
                uint32_t r0, r1, r2, r3;
                ldsm4t(r0, r1, r2, r3, vtb + (krow * FS_ST + ncol) * 2);
                MMA_F16(oacc[nf2 * 2],     pa[0], pa[1], pa[2], pa[3], r0, r1);
                MMA_F16(oacc[nf2 * 2 + 1], pa[0], pa[1], pa[2], pa[3], r2, r3);
            }
        }
    }

    float inv0 = 1.f / l0r, inv1 = 1.f / l1r;
    __half* Ob = O + (size_t)(b * NHW) * ND + hh * HDIM;
    #pragma unroll
    for (int nt = 0; nt < 8; nt++) {
        int col = nt * 8 + 2 * lc;
        *(__half2*)&Ob[(size_t)(qrow0 + lr    ) * ND + col] =
            __floats2half2_rn(oacc[nt][0] * inv0, oacc[nt][1] * inv0);
        *(__half2*)&Ob[(size_t)(qrow0 + lr + 8) * ND + col] =
            __floats2half2_rn(oacc[nt][2] * inv1, oacc[nt][3] * inv1);
    }
}

// ================= small kernels =================
__device__ __forceinline__ float2 blk_reduce2(float a, float b) {
    __shared__ float sha[9], shb[9];
    int lane = threadIdx.x & 31, w = threadIdx.x >> 5;
    #pragma unroll
    for (int o = 16; o; o >>= 1) {
        a += __shfl_down_sync(0xffffffffu, a, o);
        b += __shfl_down_sync(0xffffffffu, b, o);
    }
    if (!lane) { sha[w] = a; shb[w] = b; }
    __syncthreads();
    if (threadIdx.x == 0) {
        int nw = blockDim.x >> 5;
        float ta = 0.f, tb = 0.f;
        for (int i = 0; i < nw; i++) { ta += sha[i]; tb += shb[i]; }
        sha[8] = ta; shb[8] = tb;
    }
    __syncthreads();
    float2 r = make_float2(sha[8], shb[8]);
    __syncthreads();
    return r;
}

struct CvtSegs {
    const float* src[13];
    __half* dst[13];
    int n[13];
    int cols[13];
    int dstld[13];
    float scale[13];
};
__global__ void cvt_k(CvtSegs cs) {
    int seg = blockIdx.y;
    int n = cs.n[seg];
    int cols = cs.cols[seg], dstld = cs.dstld[seg];
    float sc = cs.scale[seg];
    const float* s = cs.src[seg];
    __half* d = cs.dst[seg];
    for (int i = blockIdx.x * blockDim.x + threadIdx.x; i < n; i += gridDim.x * blockDim.x) {
        int r = i / cols, c = i - r * cols;
        d[(size_t)r * dstld + c] = __float2half(s[i] * sc);
    }
}

__global__ void gn_stats_k(const float* __restrict__ x, float* __restrict__ mean,
                           float* __restrict__ rstd) {
    int bg = blockIdx.x;
    const float* p = x + (size_t)bg * 16384;
    float s = 0.f, s2 = 0.f;
    for (int i = threadIdx.x; i < 16384; i += 256) {
        float v = p[i];
        s += v; s2 += v * v;
    }
    float2 r = blk_reduce2(s, s2);
    if (threadIdx.x == 0) {
        float mu  = r.x * (1.f / 16384.f);
        float var = r.y * (1.f / 16384.f) - mu * mu;
        mean[bg] = mu;
        rstd[bg] = rsqrtf(var + EPSV);
    }
}

__global__ void gn_apply_k(const float* __restrict__ x, const float* __restrict__ gamma,
                           const float* __restrict__ beta, const float* __restrict__ mean,
                           const float* __restrict__ rstd, __half* __restrict__ xn) {
    __shared__ float tile[32][33];
    int b = blockIdx.z;
    int c0 = blockIdx.y * 32, hw0 = blockIdx.x * 32;
    int c = c0 + threadIdx.y, hw = hw0 + threadIdx.x;
    float v = x[((size_t)b * NC + c) * NHW + hw];
    int grp = c >> 4;
    float mu = mean[b * 32 + grp], rs = rstd[b * 32 + grp];
    tile[threadIdx.y][threadIdx.x] = (v - mu) * rs * gamma[c] + beta[c];
    __syncthreads();
    xn[((size_t)b * NHW + hw0 + threadIdx.y) * ND + c0 + threadIdx.x] =
        __float2half(tile[threadIdx.x][threadIdx.y]);
}

__global__ void ln_k(const float* __restrict__ x, const float* __restrict__ g,
                     const float* __restrict__ b, __half* __restrict__ y) {
    size_t row = blockIdx.x;
    const float2* xr = (const float2*)(x + row * ND);
    int t = threadIdx.x;
    float2 v = xr[t];
    float2 r = blk_reduce2(v.x + v.y, v.x * v.x + v.y * v.y);
    float mu = r.x * (1.f / ND);
    float rs = rsqrtf(r.y * (1.f / ND) - mu * mu + EPSV);
    float n0 = (v.x - mu) * rs * g[2 * t]     + b[2 * t];
    float n1 = (v.y - mu) * rs * g[2 * t + 1] + b[2 * t + 1];
    ((__half2*)(y + row * ND))[t] = __floats2half2_rn(n0, n1);
}

__global__ void out_add_k(const float* __restrict__ t, const float* __restrict__ x_in,
                          float* __restrict__ out) {
    __shared__ float tile[32][33];
    int b = blockIdx.z;
    int c0 = blockIdx.x * 32, hw0 = blockIdx.y * 32;
    tile[threadIdx.y][threadIdx.x] =
        t[((size_t)b * NHW + hw0 + threadIdx.y) * ND + c0 + threadIdx.x];
    __syncthreads();
    size_t o = ((size_t)b * NC + c0 + threadIdx.y) * NHW + hw0 + threadIdx.x;
    out[o] = tile[threadIdx.x][threadIdx.y] + x_in[o];
}

// ================= host =================
template<int OUTMODE>
static void hg(const __half* A, const __half* B, float* C, __half* C16,
               int M, int N, int K, int lda, int ldb, int ldc,
               const float* bias, const float* res, int gelu) {
    static bool attr_set = false;
    if (!attr_set) {
        cudaFuncSetAttribute(hgemm_k<OUTMODE>,
                             cudaFuncAttributeMaxDynamicSharedMemorySize, G_SMEM);
        attr_set = true;
    }
    dim3 grid(N / 128, (M + 127) / 128);
    hgemm_k<OUTMODE><<<grid, 256, G_SMEM>>>(A, B, C, C16, M, K, lda, ldb, ldc,
                                            bias, res, gelu);
}

extern "C" void kernel_launch(void* const* d_in, const int* in_sizes, int n_in,
                              void* d_out, int out_size) {
    const float* x      = (const float*)d_in[0];
    const float* ctx    = (const float*)d_in[1];
    const float* gn_g   = (const float*)d_in[2];
    const float* gn_b   = (const float*)d_in[3];
    const float* pin_w  = (const float*)d_in[4];
    const float* pin_b  = (const float*)d_in[5];
    const float* ln1_g  = (const float*)d_in[6];
    const float* ln1_b  = (const float*)d_in[7];
    const float* q1_w   = (const float*)d_in[8];
    const float* k1_w   = (const float*)d_in[9];
    const float* v1_w   = (const float*)d_in[10];
    const float* o1_w   = (const float*)d_in[11];
    const float* o1_b   = (const float*)d_in[12];
    const float* ln2_g  = (const float*)d_in[13];
    const float* ln2_b  = (const float*)d_in[14];
    const float* q2_w   = (const float*)d_in[15];
    const float* k2_w   = (const float*)d_in[16];
    const float* v2_w   = (const float*)d_in[17];
    const float* o2_w   = (const float*)d_in[18];
    const float* o2_b   = (const float*)d_in[19];
    const float* ln3_g  = (const float*)d_in[20];
    const float* ln3_b  = (const float*)d_in[21];
    const float* ff1_w  = (const float*)d_in[22];
    const float* ff1_b  = (const float*)d_in[23];
    const float* ff2_w  = (const float*)d_in[24];
    const float* ff2_b  = (const float*)d_in[25];
    const float* pout_w = (const float*)d_in[26];
    const float* pout_b = (const float*)d_in[27];
    float* out = (float*)d_out;

    float *h, *po, *gmean, *grstd;
    __half *xn, *hn, *h16, *qkv, *q, *kv, *ao, *ff, *w16, *ctx16;
    cudaGetSymbolAddress((void**)&h,     g_h);
    cudaGetSymbolAddress((void**)&po,    g_po);
    cudaGetSymbolAddress((void**)&xn,    g_xn);
    cudaGetSymbolAddress((void**)&hn,    g_hn);
    cudaGetSymbolAddress((void**)&h16,   g_h16);
    cudaGetSymbolAddress((void**)&qkv,   g_qkv);
    cudaGetSymbolAddress((void**)&q,     g_q);
    cudaGetSymbolAddress((void**)&kv,    g_kv);
    cudaGetSymbolAddress((void**)&ao,    g_ao);
    cudaGetSymbolAddress((void**)&ff,    g_ff);
    cudaGetSymbolAddress((void**)&w16,   g_w16);
    cudaGetSymbolAddress((void**)&ctx16, g_ctx16);
    cudaGetSymbolAddress((void**)&gmean, g_gmean);
    cudaGetSymbolAddress((void**)&grstd, g_grstd);

    dim3 t32(32, 32);

    static bool attr = false;
    if (!attr) {
        cudaFuncSetAttribute(flash_attn_k<16, 1024, 1024>,
                             cudaFuncAttributeMaxDynamicSharedMemorySize, FA_SMEM);
        cudaFuncSetAttribute(flash_attn_k<2, 77, 77>,
                             cudaFuncAttributeMaxDynamicSharedMemorySize, FA_SMEM);
        attr = true;
    }

    // 0) fp16 conversions: weights (QKV packed, attn scale folded) + ctx
    {
        CvtSegs cs;
        const float* srcs[13] = {pin_w, q1_w, k1_w, v1_w, o1_w, q2_w, o2_w, pout_w,
                                 k2_w, v2_w, ff1_w, ff2_w, ctx};
        __half* dsts[13] = {w16 + WT_PIN, w16 + WT_QKV, w16 + WT_QKV + 512,
                            w16 + WT_QKV + 1024, w16 + WT_O1, w16 + WT_Q2,
                            w16 + WT_O2, w16 + WT_POUT,
                            w16 + WT_KV2, w16 + WT_KV2 + 512,
                            w16 + WT_FF1, w16 + WT_FF2, ctx16};
        int ns[13]   = {262144, 262144, 262144, 262144, 262144, 262144, 262144, 262144,
                        393216, 393216, 1048576, 1048576, 473088};
        int cols[13] = {512, 512, 512, 512, 512, 512, 512, 512,
                        512, 512, 2048, 512, 768};
        int lds[13]  = {512, 1536, 1536, 1536, 512, 512, 512, 512,
                        1024, 1024, 2048, 512, 768};
        float scs[13] = {1.f, 0.125f, 1.f, 1.f, 1.f, 0.125f, 1.f, 1.f,
                         1.f, 1.f, 1.f, 1.f, 1.f};
        for (int i = 0; i < 13; i++) {
            cs.src[i] = srcs[i]; cs.dst[i] = dsts[i]; cs.n[i] = ns[i];
            cs.cols[i] = cols[i]; cs.dstld[i] = lds[i]; cs.scale[i] = scs[i];
        }
        cvt_k<<<dim3(256, 13), 256>>>(cs);
    }

    // 1) GroupNorm + transpose to token-major (fp16 out)
    gn_stats_k<<<NB * 32, 256>>>(x, gmean, grstd);
    gn_apply_k<<<dim3(NHW / 32, NC / 32, NB), t32>>>(x, gn_g, gn_b, gmean, grstd, xn);

    // 2) proj_in
    hg<0>(xn, w16 + WT_PIN, h, nullptr, NTOK, ND, ND, ND, ND, ND, pin_b, nullptr, 0);

    // 3) self-attention: fused QKV (q pre-scaled), flash, out-proj
    ln_k<<<NTOK, 256>>>(h, ln1_g, ln1_b, hn);
    hg<1>(hn, w16 + WT_QKV, nullptr, qkv, NTOK, 1536, ND, ND, 1536, 1536,
          nullptr, nullptr, 0);
    flash_attn_k<16, 1024, 1024><<<dim3(8, 64), 256, FA_SMEM>>>(
        qkv, qkv + 512, qkv + 1024, ao, 1536, 1536);
    hg<0>(ao, w16 + WT_O1, h, nullptr, NTOK, ND, ND, ND, ND, ND, o1_b, h, 0);

    // 4) cross-attention: q proj + fused ctx KV + flash + out-proj
    ln_k<<<NTOK, 256>>>(h, ln2_g, ln2_b, hn);
    hg<1>(hn, w16 + WT_Q2, nullptr, q, NTOK, ND, ND, ND, ND, ND, nullptr, nullptr, 0);
    hg<1>(ctx16, w16 + WT_KV2, nullptr, kv, NB * NL, 1024, NDC, NDC, 1024, 1024,
          nullptr, nullptr, 0);
    flash_attn_k<2, 77, 77><<<dim3(8, 64), 256, FA_SMEM>>>(
        q, kv, kv + 512, ao, 512, 1024);
    hg<0>(ao, w16 + WT_O2, h, nullptr, NTOK, ND, ND, ND, ND, ND, o2_b, h, 0);

    // 5) feed-forward
    ln_k<<<NTOK, 256>>>(h, ln3_g, ln3_b, hn);
    hg<1>(hn, w16 + WT_FF1, nullptr, ff, NTOK, NFF, ND, ND, NFF, NFF, ff1_b, nullptr, 1);
    hg<2>(ff, w16 + WT_FF2, h, h16, NTOK, ND, NFF, NFF, ND, ND, ff2_b, h, 0);

    // 6) proj_out + input residual
    hg<0>(h16, w16 + WT_POUT, po, nullptr, NTOK, NC, ND, ND, NC, NC, pout_b, nullptr, 0);
    out_add_k<<<dim3(NC / 32, NHW / 32, NB), t32>>>(po, x, out);
}

// round 17
// speedup vs baseline: 1.7723x; 1.0237x over previous
#include <cuda_runtime.h>
#include <cuda_fp16.h>
#include <math.h>
#include <stdint.h>

// ---------------- problem constants ----------------
#define NB    8
#define NC    512
#define NHW   1024
#define NTOK  8192
#define ND    512
#define NDC   768
#define NL    77
#define NHEAD 8
#define HDIM  64
#define NFF   2048
#define EPSV  1e-5f

// ---------------- scratch ----------------
__device__ float  g_h  [(size_t)NTOK*ND];
__device__ float  g_po [(size_t)NTOK*ND];
__device__ __half g_xn [(size_t)NTOK*ND];
__device__ __half g_hn [(size_t)NTOK*ND];
__device__ __half g_h16[(size_t)NTOK*ND];
__device__ __half g_qkv[(size_t)NTOK*1536];
__device__ __half g_q  [(size_t)NTOK*ND];
__device__ __half g_kv [(size_t)640*1024];
__device__ __half g_ao [(size_t)NTOK*ND];
__device__ __half g_ff [(size_t)NTOK*NFF];
__device__ __half g_w16[4980736];
__device__ __half g_ctx16[616*768];
__device__ float  g_gmean[NB*32];
__device__ float  g_grstd[NB*32];

// w16 pool offsets (halves)
#define WT_PIN  0
#define WT_QKV  262144
#define WT_O1   1048576
#define WT_Q2   1310720
#define WT_O2   1572864
#define WT_POUT 1835008
#define WT_KV2  2097152
#define WT_FF1  2883584
#define WT_FF2  3932160

// ---------------- PTX helpers ----------------
__device__ __forceinline__ uint32_t smem_u32(const void* p) {
    uint32_t a;
    asm("{ .reg .u64 t; cvta.to.shared.u64 t, %1; cvt.u32.u64 %0, t; }" : "=r"(a) : "l"(p));
    return a;
}
__device__ __forceinline__ uint32_t h2_u32(__half2 h) {
    union { __half2 h; uint32_t u; } c;
    c.h = h;
    return c.u;
}
__device__ __forceinline__ void cp16(uint32_t dst, const void* src, bool pred) {
    int sz = pred ? 16 : 0;
    asm volatile("cp.async.cg.shared.global [%0], [%1], 16, %2;\n" :: "r"(dst), "l"(src), "r"(sz));
}
__device__ __forceinline__ void ldsm4(uint32_t& r0, uint32_t& r1, uint32_t& r2, uint32_t& r3,
                                      uint32_t a) {
    asm volatile("ldmatrix.sync.aligned.m8n8.x4.shared.b16 {%0,%1,%2,%3}, [%4];"
                 : "=r"(r0), "=r"(r1), "=r"(r2), "=r"(r3) : "r"(a));
}
__device__ __forceinline__ void ldsm4t(uint32_t& r0, uint32_t& r1, uint32_t& r2, uint32_t& r3,
                                       uint32_t a) {
    asm volatile("ldmatrix.sync.aligned.m8n8.x4.trans.shared.b16 {%0,%1,%2,%3}, [%4];"
                 : "=r"(r0), "=r"(r1), "=r"(r2), "=r"(r3) : "r"(a));
}
#define MMA_F16(acc, a0,a1,a2,a3, b0,b1) \
    asm volatile("mma.sync.aligned.m16n8k16.row.col.f32.f16.f16.f32 " \
        "{%0,%1,%2,%3}, {%4,%5,%6,%7}, {%8,%9}, {%0,%1,%2,%3};" \
        : "+f"((acc)[0]), "+f"((acc)[1]), "+f"((acc)[2]), "+f"((acc)[3]) \
        : "r"(a0), "r"(a1), "r"(a2), "r"(a3), "r"(b0), "r"(b1))

// ================= fp16 warp-MMA GEMM (128x128, 4-stage, 2 CTAs/SM) =======
// C = A[M,K] @ B[K,N] (+bias, +res, gelu). fp16 in, fp32 accumulate.
// OUTMODE: 0=f32 C, 1=f16 C16, 2=both.
#define SAH 40                  // A smem row stride (halves)
#define SBH 136                 // B smem row stride (halves)
#define AH  (128*SAH)
#define BH  (32*SBH)
#define STH (AH + BH)
#define NSTG 4
#define G_SMEM (NSTG*STH*2)

template<int OUTMODE>
__global__ __launch_bounds__(256, 2)
void hgemm_k(const __half* __restrict__ A, const __half* __restrict__ Bm,
             float* __restrict__ C, __half* __restrict__ C16,
             int M, int K, int lda, int ldb, int ldc,
             const float* __restrict__ bias, const float* __restrict__ res,
             int gelu) {
    extern __shared__ __half smh[];

    int tid = threadIdx.x;
    int warp = tid >> 5, lane = tid & 31;
    int wm = warp & 3, wn = warp >> 2;
    int lr = lane >> 2, lc = lane & 3;
    int l8 = lane & 7, grp = lane >> 3;
    int m0 = blockIdx.y * 128, n0 = blockIdx.x * 128;

    float acc[2][8][4];
    #pragma unroll
    for (int i = 0; i < 2; i++)
        #pragma unroll
        for (int j = 0; j < 8; j++)
            #pragma unroll
            for (int l = 0; l < 4; l++) acc[i][j][l] = 0.f;

    int KT = K >> 5;

    auto load_tile = [&](int st, int kt) {
        __half* As = smh + st * STH;
        __half* Bs = As + AH;
        int k0 = kt << 5;
        #pragma unroll
        for (int i = 0; i < 2; i++) {      // A: 128 rows x 4 chunks (8 halves)
            int idx = tid + i * 256;
            int r = idx >> 2, c = idx & 3;
            int gm = m0 + r;
            int gs = gm < M ? gm : M - 1;
            cp16(smem_u32(As + r * SAH + c * 8),
                 A + (size_t)gs * lda + k0 + c * 8, gm < M);
        }
        #pragma unroll
        for (int i = 0; i < 2; i++) {      // B: 32 k-rows x 16 chunks
            int idx = tid + i * 256;
            int r = idx >> 4, c = idx & 15;
            cp16(smem_u32(Bs + r * SBH + c * 8),
                 Bm + (size_t)(k0 + r) * ldb + n0 + c * 8, true);
        }
        asm volatile("cp.async.commit_group;\n" ::: "memory");
    };

    // prologue: 3 tiles in flight (KT >= 3 for all shapes used)
    load_tile(0, 0);
    load_tile(1, 1 < KT ? 1 : KT - 1);
    load_tile(2, 2 < KT ? 2 : KT - 1);

    uint32_t aoff[2], boff[4];
    #pragma unroll
    for (int mt = 0; mt < 2; mt++) {
        int arow = wm * 32 + mt * 16 + (grp & 1) * 8 + l8;
        aoff[mt] = (arow * SAH + (grp >> 1) * 8) * 2;
    }
    #pragma unroll
    for (int nf2 = 0; nf2 < 4; nf2++) {
        int brow = (grp & 1) * 8 + l8;
        int bcol = wn * 64 + nf2 * 16 + (grp >> 1) * 8;
        boff[nf2] = (AH + brow * SBH + bcol) * 2;
    }

    for (int kt = 0; kt < KT; kt++) {
        if (kt < KT - 2)       { asm volatile("cp.async.wait_group 2;\n" ::: "memory"); }
        else if (kt == KT - 2) { asm volatile("cp.async.wait_group 1;\n" ::: "memory"); }
        else                   { asm volatile("cp.async.wait_group 0;\n" ::: "memory"); }
        __syncthreads();
        if (kt + 3 < KT) load_tile((kt + 3) % NSTG, kt + 3);

        uint32_t sbase = smem_u32(smh + (kt % NSTG) * STH);
        #pragma unroll
        for (int s16 = 0; s16 < 2; s16++) {
            uint32_t ka = sbase + s16 * 32;
            uint32_t kb = sbase + s16 * 16 * SBH * 2;
            uint32_t a[2][4];
            ldsm4(a[0][0], a[0][1], a[0][2], a[0][3], ka + aoff[0]);
            ldsm4(a[1][0], a[1][1], a[1][2], a[1][3], ka + aoff[1]);
            uint32_t bq[8][2];
            #pragma unroll
            for (int nf2 = 0; nf2 < 4; nf2++) {
                uint32_t r0, r1, r2, r3;
                ldsm4t(r0, r1, r2, r3, kb + boff[nf2]);
                bq[nf2 * 2][0] = r0;     bq[nf2 * 2][1] = r1;
                bq[nf2 * 2 + 1][0] = r2; bq[nf2 * 2 + 1][1] = r3;
            }
            #pragma unroll
            for (int mt = 0; mt < 2; mt++)
                #pragma unroll
                for (int nt = 0; nt < 8; nt++)
                    MMA_F16(acc[mt][nt], a[mt][0], a[mt][1], a[mt][2], a[mt][3],
                            bq[nt][0], bq[nt][1]);
        }
    }

    // epilogue
    #pragma unroll
    for (int mt = 0; mt < 2; mt++) {
        #pragma unroll
        for (int nt = 0; nt < 8; nt++) {
            int row0 = m0 + wm * 32 + mt * 16 + lr;
            int col0 = n0 + wn * 64 + nt * 8 + 2 * lc;
            #pragma unroll
            for (int hf = 0; hf < 2; hf++) {
                int gm = row0 + hf * 8;
                if (gm >= M) continue;
                float r0 = acc[mt][nt][hf * 2], r1 = acc[mt][nt][hf * 2 + 1];
                if (bias) { r0 += bias[col0]; r1 += bias[col0 + 1]; }
                if (res) {
                    r0 += res[(size_t)gm * ldc + col0];
                    r1 += res[(size_t)gm * ldc + col0 + 1];
                }
                if (gelu) {
                    r0 = 0.5f * r0 * (1.f + erff(r0 * 0.70710678118654752f));
                    r1 = 0.5f * r1 * (1.f + erff(r1 * 0.70710678118654752f));
                }
                if (OUTMODE == 0 || OUTMODE == 2) {
                    C[(size_t)gm * ldc + col0] = r0;
                    C[(size_t)gm * ldc + col0 + 1] = r1;
                }
                if (OUTMODE >= 1)
                    *(__half2*)&C16[(size_t)gm * ldc + col0] = __floats2half2_rn(r0, r1);
            }
        }
    }
}

// ================= fused flash attention (fp16) ===========================
#define FS_ST 72
#define KV_STG (64*FS_ST)
#define FA_SMEM ((2*KV_STG + 2*KV_STG + 128*FS_ST) * 2)

template<int NT, int KVLEN, int KVTOK>
__global__ __launch_bounds__(256, 2)
void flash_attn_k(const __half* __restrict__ Q, const __half* __restrict__ K,
                  const __half* __restrict__ V, __half* __restrict__ O,
                  int ldq, int ldkv) {
    constexpr bool MASK = (KVLEN & 63) != 0;
    extern __shared__ __half smh[];
    __half* Ks = smh;
    __half* Vs = smh + 2 * KV_STG;
    __half* Ps = smh + 4 * KV_STG;

    int tid = threadIdx.x, warp = tid >> 5, lane = tid & 31;
    int lr = lane >> 2, lc = lane & 3;
    int l8 = lane & 7, grp = lane >> 3;
    int bq = blockIdx.x;
    int bh = blockIdx.y;
    int b = bh >> 3, hh = bh & 7;

    const __half* Qb = Q + (size_t)(b * NHW) * ldq + hh * HDIM;
    const __half* Kb = K + (size_t)(b * KVTOK) * ldkv + hh * HDIM;
    const __half* Vb = V + (size_t)(b * KVTOK) * ldkv + hh * HDIM;
    int qrow0 = bq * 128 + warp * 16;

    uint32_t qf[4][4];
    {
        const uint32_t* q0 = (const uint32_t*)(Qb + (size_t)(qrow0 + lr    ) * ldq);
        const uint32_t* q1 = (const uint32_t*)(Qb + (size_t)(qrow0 + lr + 8) * ldq);
        #pragma unroll
        for (int kf = 0; kf < 4; kf++) {
            qf[kf][0] = q0[kf * 8 + lc];
            qf[kf][1] = q1[kf * 8 + lc];
            qf[kf][2] = q0[kf * 8 + 4 + lc];
            qf[kf][3] = q1[kf * 8 + 4 + lc];
        }
    }

    float oacc[8][4];
    #pragma unroll
    for (int i = 0; i < 8; i++)
        #pragma unroll
        for (int j = 0; j < 4; j++) oacc[i][j] = 0.f;
    float m0r = -1e30f, m1r = -1e30f, l0r = 0.f, l1r = 0.f;

    auto load_kv = [&](int st, int j) {
        int t0 = j * 64;
        #pragma unroll
        for (int i = 0; i < 2; i++) {
            int idx = tid + i * 256;
            int r = idx >> 3, c = idx & 7;
            bool ok = (t0 + r) < KVLEN;
            cp16(smem_u32(Ks + st * KV_STG + r * FS_ST + c * 8),
                 Kb + (size_t)(t0 + r) * ldkv + c * 8, ok);
        }
        #pragma unroll
        for (int i = 0; i < 2; i++) {
            int idx = tid + i * 256;
            int r = idx >> 3, c = idx & 7;
            bool ok = (t0 + r) < KVLEN;
            cp16(smem_u32(Vs + st * KV_STG + r * FS_ST + c * 8),
                 Vb + (size_t)(t0 + r) * ldkv + c * 8, ok);
        }
        asm volatile("cp.async.commit_group;\n" ::: "memory");
    };

    load_kv(0, 0);
    #pragma unroll 1
    for (int j = 0; j < NT; j++) {
        int st = j & 1;
        __syncthreads();
        if (j + 1 < NT) {
            load_kv(st ^ 1, j + 1);
            asm volatile("cp.async.wait_group 1;\n" ::: "memory");
        } else {
            asm volatile("cp.async.wait_group 0;\n" ::: "memory");
        }
        __syncthreads();
        uint32_t ktb = smem_u32(Ks + st * KV_STG);
        uint32_t vtb = smem_u32(Vs + st * KV_STG);

        float sacc[8][4];
        #pragma unroll
        for (int i = 0; i < 8; i++)
            #pragma unroll
            for (int l = 0; l < 4; l++) sacc[i][l] = 0.f;
        #pragma unroll
        for (int kf = 0; kf < 4; kf++) {
            #pragma unroll
            for (int nf2 = 0; nf2 < 4; nf2++) {
                int nrow = nf2 * 16 + (grp >> 1) * 8 + l8;
                int kcol = kf * 16 + (grp & 1) * 8;
                uint32_t r0, r1, r2, r3;
                ldsm4(r0, r1, r2, r3, ktb + (nrow * FS_ST + kcol) * 2);
                MMA_F16(sacc[nf2 * 2],     qf[kf][0], qf[kf][1], qf[kf][2], qf[kf][3], r0, r1);
                MMA_F16(sacc[nf2 * 2 + 1], qf[kf][0], qf[kf][1], qf[kf][2], qf[kf][3], r2, r3);
            }
        }

        if (MASK && j == NT - 1) {
            #pragma unroll
            for (int nt = 0; nt < 8; nt++) {
                int c0 = j * 64 + nt * 8 + 2 * lc;
                if (c0     >= KVLEN) { sacc[nt][0] = -1e30f; sacc[nt][2] = -1e30f; }
                if (c0 + 1 >= KVLEN) { sacc[nt][1] = -1e30f; sacc[nt][3] = -1e30f; }
            }
        }

        float mx0 = -1e30f, mx1 = -1e30f;
        #pragma unroll
        for (int nt = 0; nt < 8; nt++) {
            mx0 = fmaxf(mx0, fmaxf(sacc[nt][0], sacc[nt][1]));
            mx1 = fmaxf(mx1, fmaxf(sacc[nt][2], sacc[nt][3]));
        }
        mx0 = fmaxf(mx0, __shfl_xor_sync(0xffffffffu, mx0, 1));
        mx0 = fmaxf(mx0, __shfl_xor_sync(0xffffffffu, mx0, 2));
        mx1 = fmaxf(mx1, __shfl_xor_sync(0xffffffffu, mx1, 1));
        mx1 = fmaxf(mx1, __shfl_xor_sync(0xffffffffu, mx1, 2));
        float mn0 = fmaxf(m0r, mx0), mn1 = fmaxf(m1r, mx1);
        float f0 = __expf(m0r - mn0), f1 = __expf(m1r - mn1);
        float s0 = 0.f, s1 = 0.f;
        int prow = warp * 16 + lr;
        uint32_t* Ps32 = (uint32_t*)Ps;
        #pragma unroll
        for (int nt = 0; nt < 8; nt++) {
            float p00 = __expf(sacc[nt][0] - mn0);
            float p01 = __expf(sacc[nt][1] - mn0);
            float p10 = __expf(sacc[nt][2] - mn1);
            float p11 = __expf(sacc[nt][3] - mn1);
            s0 += p00 + p01; s1 += p10 + p11;
            Ps32[(prow    ) * (FS_ST / 2) + nt * 4 + lc] = h2_u32(__floats2half2_rn(p00, p01));
            Ps32[(prow + 8) * (FS_ST / 2) + nt * 4 + lc] = h2_u32(__floats2half2_rn(p10, p11));
            oacc[nt][0] *= f0; oacc[nt][1] *= f0;
            oacc[nt][2] *= f1; oacc[nt][3] *= f1;
        }
        s0 += __shfl_xor_sync(0xffffffffu, s0, 1);
        s0 += __shfl_xor_sync(0xffffffffu, s0, 2);
        s1 += __shfl_xor_sync(0xffffffffu, s1, 1);
        s1 += __shfl_xor_sync(0xffffffffu, s1, 2);
        l0r = l0r * f0 + s0; l1r = l1r * f1 + s1;
        m0r = mn0; m1r = mn1;

        uint32_t psb = smem_u32(Ps);
        #pragma unroll
        for (int kf = 0; kf < 4; kf++) {
            uint32_t pa[4];
            {
                int arow = warp * 16 + (grp & 1) * 8 + l8;
                int acol = kf * 16 + (grp >> 1) * 8;
                ldsm4(pa[0], pa[1], pa[2], pa[3], psb + (arow * FS_ST + acol) * 2);
            }
            #pragma unroll
            for (int nf2 = 0; nf2 < 4; nf2++) {
                int krow = kf * 16 + (grp & 1) * 8 + l8;
                int ncol = nf2 * 16 + (grp >> 1) * 8;
                uint32_t r0, r1, r2, r3;
                ldsm4t(r0, r1, r2, r3, vtb + (krow * FS_ST + ncol) * 2);
                MMA_F16(oacc[nf2 * 2],     pa[0], pa[1], pa[2], pa[3], r0, r1);
                MMA_F16(oacc[nf2 * 2 + 1], pa[0], pa[1], pa[2], pa[3], r2, r3);
            }
        }
    }

    float inv0 = 1.f / l0r, inv1 = 1.f / l1r;
    __half* Ob = O + (size_t)(b * NHW) * ND + hh * HDIM;
    #pragma unroll
    for (int nt = 0; nt < 8; nt++) {
        int col = nt * 8 + 2 * lc;
        *(__half2*)&Ob[(size_t)(qrow0 + lr    ) * ND + col] =
            __floats2half2_rn(oacc[nt][0] * inv0, oacc[nt][1] * inv0);
        *(__half2*)&Ob[(size_t)(qrow0 + lr + 8) * ND + col] =
            __floats2half2_rn(oacc[nt][2] * inv1, oacc[nt][3] * inv1);
    }
}

// ================= small kernels =================
__device__ __forceinline__ float2 blk_reduce2(float a, float b) {
    __shared__ float sha[9], shb[9];
    int lane = threadIdx.x & 31, w = threadIdx.x >> 5;
    #pragma unroll
    for (int o = 16; o; o >>= 1) {
        a += __shfl_down_sync(0xffffffffu, a, o);
        b += __shfl_down_sync(0xffffffffu, b, o);
    }
    if (!lane) { sha[w] = a; shb[w] = b; }
    __syncthreads();
    if (threadIdx.x == 0) {
        int nw = blockDim.x >> 5;
        float ta = 0.f, tb = 0.f;
        for (int i = 0; i < nw; i++) { ta += sha[i]; tb += shb[i]; }
        sha[8] = ta; shb[8] = tb;
    }
    __syncthreads();
    float2 r = make_float2(sha[8], shb[8]);
    __syncthreads();
    return r;
}

struct CvtSegs {
    const float* src[13];
    __half* dst[13];
    int n[13];
    int cols[13];
    int dstld[13];
    float scale[13];
};
__global__ void cvt_k(CvtSegs cs) {
    int seg = blockIdx.y;
    int n = cs.n[seg];
    int cols = cs.cols[seg], dstld = cs.dstld[seg];
    float sc = cs.scale[seg];
    const float* s = cs.src[seg];
    __half* d = cs.dst[seg];
    for (int i = blockIdx.x * blockDim.x + threadIdx.x; i < n; i += gridDim.x * blockDim.x) {
        int r = i / cols, c = i - r * cols;
        d[(size_t)r * dstld + c] = __float2half(s[i] * sc);
    }
}

__global__ void gn_stats_k(const float* __restrict__ x, float* __restrict__ mean,
                           float* __restrict__ rstd) {
    int bg = blockIdx.x;
    const float* p = x + (size_t)bg * 16384;
    float s = 0.f, s2 = 0.f;
    for (int i = threadIdx.x; i < 16384; i += 256) {
        float v = p[i];
        s += v; s2 += v * v;
    }
    float2 r = blk_reduce2(s, s2);
    if (threadIdx.x == 0) {
        float mu  = r.x * (1.f / 16384.f);
        float var = r.y * (1.f / 16384.f) - mu * mu;
        mean[bg] = mu;
        rstd[bg] = rsqrtf(var + EPSV);
    }
}

__global__ void gn_apply_k(const float* __restrict__ x, const float* __restrict__ gamma,
                           const float* __restrict__ beta, const float* __restrict__ mean,
                           const float* __restrict__ rstd, __half* __restrict__ xn) {
    __shared__ float tile[32][33];
    int b = blockIdx.z;
    int c0 = blockIdx.y * 32, hw0 = blockIdx.x * 32;
    int c = c0 + threadIdx.y, hw = hw0 + threadIdx.x;
    float v = x[((size_t)b * NC + c) * NHW + hw];
    int grp = c >> 4;
    float mu = mean[b * 32 + grp], rs = rstd[b * 32 + grp];
    tile[threadIdx.y][threadIdx.x] = (v - mu) * rs * gamma[c] + beta[c];
    __syncthreads();
    xn[((size_t)b * NHW + hw0 + threadIdx.y) * ND + c0 + threadIdx.x] =
        __float2half(tile[threadIdx.x][threadIdx.y]);
}

// warp-per-row LayerNorm: 8 warps/block, one row each, shuffle-only reduce
__global__ __launch_bounds__(256)
void ln_k(const float* __restrict__ x, const float* __restrict__ g,
          const float* __restrict__ b, __half* __restrict__ y) {
    int warp = threadIdx.x >> 5, lane = threadIdx.x & 31;
    size_t row = (size_t)blockIdx.x * 8 + warp;
    const float4* xr = (const float4*)(x + row * ND);
    float4 v[4];
    float s = 0.f, s2 = 0.f;
    #pragma unroll
    for (int i = 0; i < 4; i++) {
        v[i] = xr[lane + i * 32];
        s  += v[i].x + v[i].y + v[i].z + v[i].w;
        s2 += v[i].x * v[i].x + v[i].y * v[i].y + v[i].z * v[i].z + v[i].w * v[i].w;
    }
    #pragma unroll
    for (int o = 16; o; o >>= 1) {
        s  += __shfl_xor_sync(0xffffffffu, s, o);
        s2 += __shfl_xor_sync(0xffffffffu, s2, o);
    }
    float mu = s * (1.f / ND);
    float rs = rsqrtf(s2 * (1.f / ND) - mu * mu + EPSV);
    #pragma unroll
    for (int i = 0; i < 4; i++) {
        int c = (lane + i * 32) * 4;
        float4 gg = *(const float4*)&g[c];
        float4 bb = *(const float4*)&b[c];
        __half2 h0 = __floats2half2_rn((v[i].x - mu) * rs * gg.x + bb.x,
                                       (v[i].y - mu) * rs * gg.y + bb.y);
        __half2 h1 = __floats2half2_rn((v[i].z - mu) * rs * gg.z + bb.z,
                                       (v[i].w - mu) * rs * gg.w + bb.w);
        __half2* yp = (__half2*)(y + row * ND + c);
        yp[0] = h0; yp[1] = h1;
    }
}

__global__ void out_add_k(const float* __restrict__ t, const float* __restrict__ x_in,
                          float* __restrict__ out) {
    __shared__ float tile[32][33];
    int b = blockIdx.z;
    int c0 = blockIdx.x * 32, hw0 = blockIdx.y * 32;
    tile[threadIdx.y][threadIdx.x] =
        t[((size_t)b * NHW + hw0 + threadIdx.y) * ND + c0 + threadIdx.x];
    __syncthreads();
    size_t o = ((size_t)b * NC + c0 + threadIdx.y) * NHW + hw0 + threadIdx.x;
    out[o] = tile[threadIdx.x][threadIdx.y] + x_in[o];
}

// ================= host =================
template<int OUTMODE>
static void hg(const __half* A, const __half* B, float* C, __half* C16,
               int M, int N, int K, int lda, int ldb, int ldc,
               const float* bias, const float* res, int gelu) {
    static bool attr_set = false;
    if (!attr_set) {
        cudaFuncSetAttribute(hgemm_k<OUTMODE>,
                             cudaFuncAttributeMaxDynamicSharedMemorySize, G_SMEM);
        attr_set = true;
    }
    dim3 grid(N / 128, (M + 127) / 128);
    hgemm_k<OUTMODE><<<grid, 256, G_SMEM>>>(A, B, C, C16, M, K, lda, ldb, ldc,
                                            bias, res, gelu);
}

extern "C" void kernel_launch(void* const* d_in, const int* in_sizes, int n_in,
                              void* d_out, int out_size) {
    const float* x      = (const float*)d_in[0];
    const float* ctx    = (const float*)d_in[1];
    const float* gn_g   = (const float*)d_in[2];
    const float* gn_b   = (const float*)d_in[3];
    const float* pin_w  = (const float*)d_in[4];
    const float* pin_b  = (const float*)d_in[5];
    const float* ln1_g  = (const float*)d_in[6];
    const float* ln1_b  = (const float*)d_in[7];
    const float* q1_w   = (const float*)d_in[8];
    const float* k1_w   = (const float*)d_in[9];
    const float* v1_w   = (const float*)d_in[10];
    const float* o1_w   = (const float*)d_in[11];
    const float* o1_b   = (const float*)d_in[12];
    const float* ln2_g  = (const float*)d_in[13];
    const float* ln2_b  = (const float*)d_in[14];
    const float* q2_w   = (const float*)d_in[15];
    const float* k2_w   = (const float*)d_in[16];
    const float* v2_w   = (const float*)d_in[17];
    const float* o2_w   = (const float*)d_in[18];
    const float* o2_b   = (const float*)d_in[19];
    const float* ln3_g  = (const float*)d_in[20];
    const float* ln3_b  = (const float*)d_in[21];
    const float* ff1_w  = (const float*)d_in[22];
    const float* ff1_b  = (const float*)d_in[23];
    const float* ff2_w  = (const float*)d_in[24];
    const float* ff2_b  = (const float*)d_in[25];
    const float* pout_w = (const float*)d_in[26];
    const float* pout_b = (const float*)d_in[27];
    float* out = (float*)d_out;

    float *h, *po, *gmean, *grstd;
    __half *xn, *hn, *h16, *qkv, *q, *kv, *ao, *ff, *w16, *ctx16;
    cudaGetSymbolAddress((void**)&h,     g_h);
    cudaGetSymbolAddress((void**)&po,    g_po);
    cudaGetSymbolAddress((void**)&xn,    g_xn);
    cudaGetSymbolAddress((void**)&hn,    g_hn);
    cudaGetSymbolAddress((void**)&h16,   g_h16);
    cudaGetSymbolAddress((void**)&qkv,   g_qkv);
    cudaGetSymbolAddress((void**)&q,     g_q);
    cudaGetSymbolAddress((void**)&kv,    g_kv);
    cudaGetSymbolAddress((void**)&ao,    g_ao);
    cudaGetSymbolAddress((void**)&ff,    g_ff);
    cudaGetSymbolAddress((void**)&w16,   g_w16);
    cudaGetSymbolAddress((void**)&ctx16, g_ctx16);
    cudaGetSymbolAddress((void**)&gmean, g_gmean);
    cudaGetSymbolAddress((void**)&grstd, g_grstd);

    dim3 t32(32, 32);

    static bool attr = false;
    if (!attr) {
        cudaFuncSetAttribute(flash_attn_k<16, 1024, 1024>,
                             cudaFuncAttributeMaxDynamicSharedMemorySize, FA_SMEM);
        cudaFuncSetAttribute(flash_attn_k<2, 77, 77>,
                             cudaFuncAttributeMaxDynamicSharedMemorySize, FA_SMEM);
        attr = true;
    }

    // 0) fp16 conversions: weights (QKV packed, attn scale folded) + ctx
    {
        CvtSegs cs;
        const float* srcs[13] = {pin_w, q1_w, k1_w, v1_w, o1_w, q2_w, o2_w, pout_w,
                                 k2_w, v2_w, ff1_w, ff2_w, ctx};
        __half* dsts[13] = {w16 + WT_PIN, w16 + WT_QKV, w16 + WT_QKV + 512,
                            w16 + WT_QKV + 1024, w16 + WT_O1, w16 + WT_Q2,
                            w16 + WT_O2, w16 + WT_POUT,
                            w16 + WT_KV2, w16 + WT_KV2 + 512,
                            w16 + WT_FF1, w16 + WT_FF2, ctx16};
        int ns[13]   = {262144, 262144, 262144, 262144, 262144, 262144, 262144, 262144,
                        393216, 393216, 1048576, 1048576, 473088};
        int cols[13] = {512, 512, 512, 512, 512, 512, 512, 512,
                        512, 512, 2048, 512, 768};
        int lds[13]  = {512, 1536, 1536, 1536, 512, 512, 512, 512,
                        1024, 1024, 2048, 512, 768};
        float scs[13] = {1.f, 0.125f, 1.f, 1.f, 1.f, 0.125f, 1.f, 1.f,
                         1.f, 1.f, 1.f, 1.f, 1.f};
        for (int i = 0; i < 13; i++) {
            cs.src[i] = srcs[i]; cs.dst[i] = dsts[i]; cs.n[i] = ns[i];
            cs.cols[i] = cols[i]; cs.dstld[i] = lds[i]; cs.scale[i] = scs[i];
        }
        cvt_k<<<dim3(256, 13), 256>>>(cs);
    }

    // 1) GroupNorm + transpose to token-major (fp16 out)
    gn_stats_k<<<NB * 32, 256>>>(x, gmean, grstd);
    gn_apply_k<<<dim3(NHW / 32, NC / 32, NB), t32>>>(x, gn_g, gn_b, gmean, grstd, xn);

    // 2) proj_in
    hg<0>(xn, w16 + WT_PIN, h, nullptr, NTOK, ND, ND, ND, ND, ND, pin_b, nullptr, 0);

    // 3) self-attention: fused QKV (q pre-scaled), flash, out-proj
    ln_k<<<NTOK / 8, 256>>>(h, ln1_g, ln1_b, hn);
    hg<1>(hn, w16 + WT_QKV, nullptr, qkv, NTOK, 1536, ND, ND, 1536, 1536,
          nullptr, nullptr, 0);
    flash_attn_k<16, 1024, 1024><<<dim3(8, 64), 256, FA_SMEM>>>(
        qkv, qkv + 512, qkv + 1024, ao, 1536, 1536);
    hg<0>(ao, w16 + WT_O1, h, nullptr, NTOK, ND, ND, ND, ND, ND, o1_b, h, 0);

    // 4) cross-attention: q proj + fused ctx KV + flash + out-proj
    ln_k<<<NTOK / 8, 256>>>(h, ln2_g, ln2_b, hn);
    hg<1>(hn, w16 + WT_Q2, nullptr, q, NTOK, ND, ND, ND, ND, ND, nullptr, nullptr, 0);
    hg<1>(ctx16, w16 + WT_KV2, nullptr, kv, NB * NL, 1024, NDC, NDC, 1024, 1024,
          nullptr, nullptr, 0);
    flash_attn_k<2, 77, 77><<<dim3(8, 64), 256, FA_SMEM>>>(
        q, kv, kv + 512, ao, 512, 1024);
    hg<0>(ao, w16 + WT_O2, h, nullptr, NTOK, ND, ND, ND, ND, ND, o2_b, h, 0);

    // 5) feed-forward
    ln_k<<<NTOK / 8, 256>>>(h, ln3_g, ln3_b, hn);
    hg<1>(hn, w16 + WT_FF1, nullptr, ff, NTOK, NFF, ND, ND, NFF, NFF, ff1_b, nullptr, 1);
    hg<2>(ff, w16 + WT_FF2, h, h16, NTOK, ND, NFF, NFF, ND, ND, ff2_b, h, 0);

    // 6) proj_out + input residual
    hg<0>(h16, w16 + WT_POUT, po, nullptr, NTOK, NC, ND, ND, NC, NC, pout_b, nullptr, 0);
    out_add_k<<<dim3(NC / 32, NHW / 32, NB), t32>>>(po, x, out);
}